// round 15
// baseline (speedup 1.0000x reference)
#include <cuda_runtime.h>
#include <cuda_bf16.h>
#include <cstdint>

// ---------------- scratch (device globals; no allocations allowed) ----------------
#define MAXNB 200000
#define MAXNC 20000
#define MAXNT 2000
#define MAXE_GAT 200000
#define MAXE_ADJ 1600000
#define SCAN_B 512

__device__ __nv_bfloat16 g_hs[(size_t)MAXNB * 128];  // hs1, later hs2
__device__ __nv_bfloat16 g_xw[(size_t)MAXNB * 128];  // GCN xw
__device__ float g_es[(size_t)MAXNB * 4];
__device__ float g_ed[(size_t)MAXNC * 4];
__device__ float g_edt[(size_t)MAXNT * 4];
__device__ float g_sb[(size_t)MAXNT * 4];
__device__ float g_wb[(size_t)MAXE_GAT * 4];
__device__ float g_dinv[MAXNB];
__device__ int g_cntc[MAXNC];
__device__ int g_offc[MAXNC + 1];
__device__ int g_cntb[MAXNB];
__device__ int g_offb[MAXNB + 1];
__device__ int g_csrc_c[MAXE_GAT];
__device__ int g_csrc_b[MAXE_ADJ];
__device__ int g_bsum[1024];
__device__ float g_v2a[128 * 4];
__device__ float g_v2b[128 * 4];
__device__ float g_wt1[128 * 128];
__device__ float g_wt2[128 * 128];
__device__ float g_wtg[128 * 128];

static __device__ __forceinline__ void red_add_v4(float* addr, float x, float y, float z, float w) {
    asm volatile("red.global.add.v4.f32 [%0], {%1,%2,%3,%4};"
                 :: "l"(addr), "f"(x), "f"(y), "f"(z), "f"(w) : "memory");
}

static __device__ __forceinline__ unsigned bf2pack(float c0, float c1) {
    unsigned r;
    asm("cvt.rn.bf16x2.f32 %0, %1, %2;" : "=r"(r) : "f"(c1), "f"(c0));
    return r;
}

static __device__ __forceinline__ uint32_t tf32r(float v) {
    uint32_t r;
    asm("cvt.rna.tf32.f32 %0, %1;" : "=r"(r) : "f"(v));
    return r;
}

// 3 weights transposed ([n][k]) + tf32-rounded, selected by blockIdx.z
__global__ void transpose_w3(const float* __restrict__ W0, const float* __restrict__ W1,
                             const float* __restrict__ W2, float* __restrict__ T0,
                             float* __restrict__ T1, float* __restrict__ T2) {
    const float* W = blockIdx.z == 0 ? W0 : (blockIdx.z == 1 ? W1 : W2);
    float* T = blockIdx.z == 0 ? T0 : (blockIdx.z == 1 ? T1 : T2);
    __shared__ float t[32][33];
    int bx = blockIdx.x * 32, by = blockIdx.y * 32;
#pragma unroll
    for (int j = 0; j < 32; j += 8)
        t[threadIdx.y + j][threadIdx.x] =
            __uint_as_float(tf32r(W[(size_t)(by + threadIdx.y + j) * 128 + bx + threadIdx.x]));
    __syncthreads();
#pragma unroll
    for (int j = 0; j < 32; j += 8)
        T[(size_t)(bx + threadIdx.y + j) * 128 + by + threadIdx.x] = t[threadIdx.x][threadIdx.y + j];
}

__global__ void precompute_v2(const float* __restrict__ Wd1, const float* __restrict__ ad1,
                              const float* __restrict__ Wd2, const float* __restrict__ ad2,
                              float* __restrict__ Va, float* __restrict__ Vb) {
    const float* W = blockIdx.x == 0 ? Wd1 : Wd2;
    const float* a = blockIdx.x == 0 ? ad1 : ad2;
    float* V = blockIdx.x == 0 ? Va : Vb;
    int d = threadIdx.x;
    float s[4] = {0.f, 0.f, 0.f, 0.f};
#pragma unroll
    for (int h = 0; h < 4; h++)
        for (int c = 0; c < 32; c++)
            s[h] += W[d * 128 + h * 32 + c] * a[h * 32 + c];
    ((float4*)V)[d] = make_float4(s[0], s[1], s[2], s[3]);
}

// ---------------- tf32 mma.sync GEMMs (32-row x 64-col warp tiles; R11 config) ------
#define AP 132
#define MMA_SMEM ((128 * AP * 2) * 4)

static __device__ __forceinline__ void mma_loop32(const uint32_t* __restrict__ Asu,
                                                  const uint32_t* __restrict__ Wsu,
                                                  int ar0, int bbase, int t,
                                                  float acc[2][8][4]) {
    int ar1 = ar0 + 8 * AP, ar2 = ar0 + 16 * AP, ar3 = ar0 + 24 * AP;
#pragma unroll 2
    for (int ks = 0; ks < 16; ks++) {
        int k0 = ks * 8;
        uint32_t a00 = Asu[ar0 + k0 + t];
        uint32_t a01 = Asu[ar1 + k0 + t];
        uint32_t a02 = Asu[ar0 + k0 + t + 4];
        uint32_t a03 = Asu[ar1 + k0 + t + 4];
        uint32_t a10 = Asu[ar2 + k0 + t];
        uint32_t a11 = Asu[ar3 + k0 + t];
        uint32_t a12 = Asu[ar2 + k0 + t + 4];
        uint32_t a13 = Asu[ar3 + k0 + t + 4];
#pragma unroll
        for (int nt = 0; nt < 8; nt++) {
            uint32_t b0 = Wsu[bbase + nt * 8 * AP + k0 + t];
            uint32_t b1 = Wsu[bbase + nt * 8 * AP + k0 + t + 4];
            asm("mma.sync.aligned.m16n8k8.row.col.f32.tf32.tf32.f32 "
                "{%0,%1,%2,%3}, {%4,%5,%6,%7}, {%8,%9}, {%0,%1,%2,%3};"
                : "+f"(acc[0][nt][0]), "+f"(acc[0][nt][1]), "+f"(acc[0][nt][2]), "+f"(acc[0][nt][3])
                : "r"(a00), "r"(a01), "r"(a02), "r"(a03), "r"(b0), "r"(b1));
            asm("mma.sync.aligned.m16n8k8.row.col.f32.tf32.tf32.f32 "
                "{%0,%1,%2,%3}, {%4,%5,%6,%7}, {%8,%9}, {%0,%1,%2,%3};"
                : "+f"(acc[1][nt][0]), "+f"(acc[1][nt][1]), "+f"(acc[1][nt][2]), "+f"(acc[1][nt][3])
                : "r"(a10), "r"(a11), "r"(a12), "r"(a13), "r"(b0), "r"(b1));
        }
    }
}

static __device__ __forceinline__ void mma_epilogue32(float acc[2][8][4], __nv_bfloat16* C,
                                                      int M, int brow, int wr, int wc,
                                                      int g, int t, float* es_out,
                                                      const float* a_s) {
    int grow[4];
    grow[0] = brow + wr * 32 + g;
    grow[1] = grow[0] + 8;
    grow[2] = grow[0] + 16;
    grow[3] = grow[0] + 24;
    bool okr[4];
#pragma unroll
    for (int s = 0; s < 4; s++) okr[s] = grow[s] < M;
    bool do_es = es_out != nullptr;
    float sv[4][2] = {{0.f, 0.f}, {0.f, 0.f}, {0.f, 0.f}, {0.f, 0.f}};
#pragma unroll
    for (int mg = 0; mg < 2; mg++) {
#pragma unroll
        for (int nt = 0; nt < 8; nt++) {
            float c0 = acc[mg][nt][0], c1 = acc[mg][nt][1];
            float c2 = acc[mg][nt][2], c3 = acc[mg][nt][3];
            int col = wc * 64 + nt * 8 + 2 * t;
            if (okr[mg * 2])
                *(unsigned*)(C + (size_t)grow[mg * 2] * 128 + col) = bf2pack(c0, c1);
            if (okr[mg * 2 + 1])
                *(unsigned*)(C + (size_t)grow[mg * 2 + 1] * 128 + col) = bf2pack(c2, c3);
            if (do_es) {
                int hl = nt >> 2;
                int cb = (wc * 2 + hl) * 32 + (nt & 3) * 8 + 2 * t;
                float av0 = __ldg(a_s + cb), av1 = __ldg(a_s + cb + 1);
                sv[mg * 2][hl]     += c0 * av0 + c1 * av1;
                sv[mg * 2 + 1][hl] += c2 * av0 + c3 * av1;
            }
        }
    }
    if (do_es) {
#pragma unroll
        for (int s = 0; s < 4; s++) {
#pragma unroll
            for (int hl = 0; hl < 2; hl++) {
                sv[s][hl] += __shfl_down_sync(~0u, sv[s][hl], 1);
                sv[s][hl] += __shfl_down_sync(~0u, sv[s][hl], 2);
            }
        }
        if (t == 0) {
#pragma unroll
            for (int s = 0; s < 4; s++) {
                if (okr[s])
                    *(float2*)(es_out + (size_t)grow[s] * 4 + wc * 2) =
                        make_float2(sv[s][0], sv[s][1]);
            }
        }
    }
}

__global__ void __launch_bounds__(256, 1)
gemm_mma(const float* __restrict__ A, const float* __restrict__ Wt,
         __nv_bfloat16* __restrict__ C, int M,
         float* __restrict__ es_out, const float* __restrict__ a_s) {
    extern __shared__ float smem[];
    float* As = smem;
    float* Ws = smem + 128 * AP;
    int tid = threadIdx.x;
    int brow = blockIdx.x * 128;
    {
        int row = tid & 127;
        int k0 = (tid >> 7) * 64;
        int grow = brow + row;
        bool ok = grow < M;
        const float4* Ar = (const float4*)(A + (size_t)grow * 128 + k0);
        const float4* Wr = (const float4*)(Wt + (size_t)row * 128 + k0);
#pragma unroll
        for (int i = 0; i < 16; i++) {
            float4 v = make_float4(0.f, 0.f, 0.f, 0.f);
            if (ok) v = Ar[i];
            uint4 tv;
            tv.x = tf32r(v.x); tv.y = tf32r(v.y); tv.z = tf32r(v.z); tv.w = tf32r(v.w);
            *(uint4*)(As + row * AP + k0 + i * 4) = tv;
            *(float4*)(Ws + row * AP + k0 + i * 4) = Wr[i];
        }
    }
    __syncthreads();

    int wid = tid >> 5, lane = tid & 31;
    int g = lane >> 2, t = lane & 3;
    int wr = wid >> 1, wc = wid & 1;
    float acc[2][8][4];
#pragma unroll
    for (int mg = 0; mg < 2; mg++)
#pragma unroll
        for (int nt = 0; nt < 8; nt++)
#pragma unroll
            for (int j = 0; j < 4; j++) acc[mg][nt][j] = 0.f;
    mma_loop32((const uint32_t*)As, (const uint32_t*)Ws,
               (wr * 32 + g) * AP, (wc * 64 + g) * AP, t, acc);
    mma_epilogue32(acc, C, M, brow, wr, wc, g, t, es_out, a_s);
}

__global__ void __launch_bounds__(256, 1)
gemm_dual(const float* __restrict__ A, const float* __restrict__ Wt0,
          const float* __restrict__ Wt1, __nv_bfloat16* __restrict__ C0,
          __nv_bfloat16* __restrict__ C1, int M,
          float* __restrict__ es_out, const float* __restrict__ a_s) {
    extern __shared__ float smem[];
    float* As = smem;
    float* Ws = smem + 128 * AP;
    int tid = threadIdx.x;
    int brow = blockIdx.x * 128;
    int row = tid & 127;
    int k0 = (tid >> 7) * 64;
    {
        int grow = brow + row;
        bool ok = grow < M;
        const float4* Ar = (const float4*)(A + (size_t)grow * 128 + k0);
#pragma unroll
        for (int i = 0; i < 16; i++) {
            float4 v = make_float4(0.f, 0.f, 0.f, 0.f);
            if (ok) v = Ar[i];
            uint4 tv;
            tv.x = tf32r(v.x); tv.y = tf32r(v.y); tv.z = tf32r(v.z); tv.w = tf32r(v.w);
            *(uint4*)(As + row * AP + k0 + i * 4) = tv;
        }
    }

    int wid = tid >> 5, lane = tid & 31;
    int g = lane >> 2, t = lane & 3;
    int wr = wid >> 1, wc = wid & 1;
    int ar0 = (wr * 32 + g) * AP;
    int bbase = (wc * 64 + g) * AP;

#pragma unroll
    for (int p = 0; p < 2; p++) {
        const float* Wt = p == 0 ? Wt0 : Wt1;
        {
            const float4* Wr = (const float4*)(Wt + (size_t)row * 128 + k0);
#pragma unroll
            for (int i = 0; i < 16; i++)
                *(float4*)(Ws + row * AP + k0 + i * 4) = Wr[i];
        }
        __syncthreads();
        float acc[2][8][4];
#pragma unroll
        for (int mg = 0; mg < 2; mg++)
#pragma unroll
            for (int nt = 0; nt < 8; nt++)
#pragma unroll
                for (int j = 0; j < 4; j++) acc[mg][nt][j] = 0.f;
        mma_loop32((const uint32_t*)As, (const uint32_t*)Ws, ar0, bbase, t, acc);
        __syncthreads();  // safe to overwrite Ws next phase
        mma_epilogue32(acc, p == 0 ? C0 : C1, M, brow, wr, wc, g, t,
                       p == 0 ? es_out : (float*)nullptr, a_s);
    }
}

// out[n,h] = x[n,:] @ V[:,h]   (warp per node)
__global__ void node_alpha(const float* __restrict__ X, const float* __restrict__ V,
                           float* __restrict__ out, int N) {
    int gt = blockIdx.x * blockDim.x + threadIdx.x;
    int n = gt >> 5, lane = gt & 31;
    if (n >= N) return;
    float4 x = ((const float4*)(X + (size_t)n * 128))[lane];
    const float4* Vv = (const float4*)V;
    float xv[4] = {x.x, x.y, x.z, x.w};
    float s0 = 0.f, s1 = 0.f, s2 = 0.f, s3 = 0.f;
#pragma unroll
    for (int j = 0; j < 4; j++) {
        float4 v = Vv[lane * 4 + j];
        s0 += xv[j] * v.x; s1 += xv[j] * v.y;
        s2 += xv[j] * v.z; s3 += xv[j] * v.w;
    }
#pragma unroll
    for (int off = 16; off; off >>= 1) {
        s0 += __shfl_down_sync(~0u, s0, off);
        s1 += __shfl_down_sync(~0u, s1, off);
        s2 += __shfl_down_sync(~0u, s2, off);
        s3 += __shfl_down_sync(~0u, s3, off);
    }
    if (lane == 0) ((float4*)out)[n] = make_float4(s0, s1, s2, s3);
}

static __device__ __forceinline__ float4 edge_w4(const float* es, const float* ed, int s, int d) {
    float4 a = ((const float4*)es)[s];
    float4 b = ((const float4*)ed)[d];
    float t0 = a.x + b.x, t1 = a.y + b.y, t2 = a.z + b.z, t3 = a.w + b.w;
    t0 = t0 > 0.f ? t0 : 0.2f * t0;
    t1 = t1 > 0.f ? t1 : 0.2f * t1;
    t2 = t2 > 0.f ? t2 : 0.2f * t2;
    t3 = t3 > 0.f ? t3 : 0.2f * t3;
    return make_float4(__expf(t0), __expf(t1), __expf(t2), __expf(t3));
}

// COO edge_w for GAT2 (small)
__global__ void edge_w(const float* __restrict__ es, const float* __restrict__ ed,
                       const int* __restrict__ src, const int* __restrict__ dst,
                       float* __restrict__ w, float* __restrict__ ssum, int E) {
    int e = blockIdx.x * blockDim.x + threadIdx.x;
    if (e >= E) return;
    int s = src[e], d = dst[e];
    float4 wv = edge_w4(es, ed, s, d);
    ((float4*)w)[e] = wv;
    red_add_v4(ssum + (size_t)d * 4, wv.x, wv.y, wv.z, wv.w);
}

// CSR edge_w + fill for GAT1
__global__ void edge_w_fill(const float* __restrict__ es, const float* __restrict__ ed,
                            const int* __restrict__ src, const int* __restrict__ dst,
                            int* __restrict__ cursor, int* __restrict__ csrc,
                            float* __restrict__ w, int E) {
    int e = blockIdx.x * blockDim.x + threadIdx.x;
    if (e >= E) return;
    int s = src[e], d = dst[e];
    float4 wv = edge_w4(es, ed, s, d);
    int p = atomicAdd(cursor + d, 1);
    csrc[p] = s;
    ((float4*)w)[p] = wv;
}

// warp per dst node: softmax-sum + gather + finalize
// 4 rows per iteration for MLP; all 4 weight components shuffled, head selected locally.
__global__ void gat_csr(const int* __restrict__ off, const int* __restrict__ csrc,
                        const float* __restrict__ wbuf, const __nv_bfloat16* __restrict__ hs,
                        const float* __restrict__ xdst, const float* __restrict__ bias,
                        float* __restrict__ out, int N) {
    int gt = blockIdx.x * blockDim.x + threadIdx.x;
    int n = gt >> 5, lane = gt & 31;
    if (n >= N) return;
    int o0 = off[n], o1 = off[n + 1];
    float sw0 = 0.f, sw1 = 0.f, sw2 = 0.f, sw3 = 0.f;
    for (int e = o0 + lane; e < o1; e += 32) {
        float4 w = ((const float4*)wbuf)[e];
        sw0 += w.x; sw1 += w.y; sw2 += w.z; sw3 += w.w;
    }
#pragma unroll
    for (int o = 16; o; o >>= 1) {
        sw0 += __shfl_xor_sync(~0u, sw0, o);
        sw1 += __shfl_xor_sync(~0u, sw1, o);
        sw2 += __shfl_xor_sync(~0u, sw2, o);
        sw3 += __shfl_xor_sync(~0u, sw3, o);
    }
    int h = lane >> 3;
    float stot = (h < 2) ? (h == 0 ? sw0 : sw1) : (h == 2 ? sw2 : sw3);
    float kinv = 0.5f / (stot + 1e-16f);
    float a0 = 0.f, a1 = 0.f, a2 = 0.f, a3 = 0.f;
    for (int base = o0; base < o1; base += 32) {
        int eidx = base + lane;
        bool v = eidx < o1;
        int s_l = v ? csrc[eidx] : 0;
        float4 w_l = v ? ((const float4*)wbuf)[eidx] : make_float4(0.f, 0.f, 0.f, 0.f);
        int cntc = min(32, o1 - base);
        int j = 0;
        for (; j + 3 < cntc; j += 4) {
            // edge indices
            int sa = __shfl_sync(~0u, s_l, j);
            int sb = __shfl_sync(~0u, s_l, j + 1);
            int sc = __shfl_sync(~0u, s_l, j + 2);
            int sd = __shfl_sync(~0u, s_l, j + 3);
            // issue all gathers early
            uint2 ra = *(const uint2*)(hs + (size_t)sa * 128 + lane * 4);
            uint2 rb = *(const uint2*)(hs + (size_t)sb * 128 + lane * 4);
            uint2 rc = *(const uint2*)(hs + (size_t)sc * 128 + lane * 4);
            uint2 rd = *(const uint2*)(hs + (size_t)sd * 128 + lane * 4);
            // full 4-component weight shuffles, local head select (correct semantics)
            float wa0 = __shfl_sync(~0u, w_l.x, j),   wa1 = __shfl_sync(~0u, w_l.y, j);
            float wa2 = __shfl_sync(~0u, w_l.z, j),   wa3 = __shfl_sync(~0u, w_l.w, j);
            float wb0 = __shfl_sync(~0u, w_l.x, j+1), wb1 = __shfl_sync(~0u, w_l.y, j+1);
            float wb2 = __shfl_sync(~0u, w_l.z, j+1), wb3 = __shfl_sync(~0u, w_l.w, j+1);
            float wc0 = __shfl_sync(~0u, w_l.x, j+2), wc1 = __shfl_sync(~0u, w_l.y, j+2);
            float wc2 = __shfl_sync(~0u, w_l.z, j+2), wc3 = __shfl_sync(~0u, w_l.w, j+2);
            float wd0 = __shfl_sync(~0u, w_l.x, j+3), wd1 = __shfl_sync(~0u, w_l.y, j+3);
            float wd2 = __shfl_sync(~0u, w_l.z, j+3), wd3 = __shfl_sync(~0u, w_l.w, j+3);
            float ka = ((h < 2) ? (h == 0 ? wa0 : wa1) : (h == 2 ? wa2 : wa3)) * kinv;
            float kb = ((h < 2) ? (h == 0 ? wb0 : wb1) : (h == 2 ? wb2 : wb3)) * kinv;
            float kc = ((h < 2) ? (h == 0 ? wc0 : wc1) : (h == 2 ? wc2 : wc3)) * kinv;
            float kd = ((h < 2) ? (h == 0 ? wd0 : wd1) : (h == 2 ? wd2 : wd3)) * kinv;
            float2 fa0 = __bfloat1622float2(*(const __nv_bfloat162*)&ra.x);
            float2 fa1 = __bfloat1622float2(*(const __nv_bfloat162*)&ra.y);
            float2 fb0 = __bfloat1622float2(*(const __nv_bfloat162*)&rb.x);
            float2 fb1 = __bfloat1622float2(*(const __nv_bfloat162*)&rb.y);
            float2 fc0 = __bfloat1622float2(*(const __nv_bfloat162*)&rc.x);
            float2 fc1 = __bfloat1622float2(*(const __nv_bfloat162*)&rc.y);
            float2 fd0 = __bfloat1622float2(*(const __nv_bfloat162*)&rd.x);
            float2 fd1 = __bfloat1622float2(*(const __nv_bfloat162*)&rd.y);
            a0 += ka * fa0.x + kb * fb0.x + kc * fc0.x + kd * fd0.x;
            a1 += ka * fa0.y + kb * fb0.y + kc * fc0.y + kd * fd0.y;
            a2 += ka * fa1.x + kb * fb1.x + kc * fc1.x + kd * fd1.x;
            a3 += ka * fa1.y + kb * fb1.y + kc * fc1.y + kd * fd1.y;
        }
        for (; j < cntc; j++) {
            int s = __shfl_sync(~0u, s_l, j);
            float w0 = __shfl_sync(~0u, w_l.x, j);
            float w1 = __shfl_sync(~0u, w_l.y, j);
            float w2 = __shfl_sync(~0u, w_l.z, j);
            float w3 = __shfl_sync(~0u, w_l.w, j);
            float wh = (h < 2) ? (h == 0 ? w0 : w1) : (h == 2 ? w2 : w3);
            float k = wh * kinv;
            uint2 raw = *(const uint2*)(hs + (size_t)s * 128 + lane * 4);
            float2 f0 = __bfloat1622float2(*(const __nv_bfloat162*)&raw.x);
            float2 f1 = __bfloat1622float2(*(const __nv_bfloat162*)&raw.y);
            a0 += k * f0.x; a1 += k * f0.y; a2 += k * f1.x; a3 += k * f1.y;
        }
    }
    float4 xv = *(const float4*)(xdst + (size_t)n * 128 + lane * 4);
    float4 bv = *(const float4*)(bias + lane * 4);
    float4 o;
    o.x = xv.x + 0.5f * bv.x + a0;
    o.y = xv.y + 0.5f * bv.y + a1;
    o.z = xv.z + 0.5f * bv.z + a2;
    o.w = xv.w + 0.5f * bv.w + a3;
    *(float4*)(out + (size_t)n * 128 + lane * 4) = o;
}

// warp per edge: out[dst] += 0.5 * alpha * hs_bf16[src]  (COO, GAT2)
__global__ void edge_aggr(const float* __restrict__ w, const float* __restrict__ ssum,
                          const int* __restrict__ src, const int* __restrict__ dst,
                          const __nv_bfloat16* __restrict__ hs, float* __restrict__ out, int E) {
    int gt = blockIdx.x * blockDim.x + threadIdx.x;
    int e = gt >> 5, lane = gt & 31;
    if (e >= E) return;
    int s = src[e], d = dst[e];
    int h = lane >> 3;
    float alpha = w[(size_t)e * 4 + h] / (ssum[(size_t)d * 4 + h] + 1e-16f);
    float k = 0.5f * alpha;
    uint2 raw = *(const uint2*)(hs + (size_t)s * 128 + lane * 4);
    float2 f0 = __bfloat1622float2(*(const __nv_bfloat162*)&raw.x);
    float2 f1 = __bfloat1622float2(*(const __nv_bfloat162*)&raw.y);
    red_add_v4(out + (size_t)d * 128 + lane * 4, k * f0.x, k * f0.y, k * f1.x, k * f1.y);
}

// out[n,c] = x[n,c] + 0.5*b[c]
__global__ void init_half_bias(const float* __restrict__ x, const float* __restrict__ b,
                               float* __restrict__ out, int N) {
    int i = blockIdx.x * blockDim.x + threadIdx.x;
    if (i >= N * 32) return;
    float4 xv = ((const float4*)x)[i];
    float4 bv = ((const float4*)b)[i & 31];
    ((float4*)out)[i] = make_float4(xv.x + 0.5f * bv.x, xv.y + 0.5f * bv.y,
                                    xv.z + 0.5f * bv.z, xv.w + 0.5f * bv.w);
}

// ---------------- CSR build ----------------
__global__ void count_dst(const int* __restrict__ dst, int* __restrict__ cnt, int E) {
    int e = blockIdx.x * blockDim.x + threadIdx.x;
    if (e < E) atomicAdd(cnt + dst[e], 1);
}

__global__ void scan1(const int* __restrict__ cnt, int* __restrict__ incl,
                      int* __restrict__ bsum, int N) {
    int i = blockIdx.x * SCAN_B + threadIdx.x;
    int lane = threadIdx.x & 31, wid = threadIdx.x >> 5;
    int v = (i < N) ? cnt[i] : 0;
    int x = v;
#pragma unroll
    for (int o = 1; o < 32; o <<= 1) {
        int t = __shfl_up_sync(~0u, x, o);
        if (lane >= o) x += t;
    }
    __shared__ int wtot[16];
    if (lane == 31) wtot[wid] = x;
    __syncthreads();
    if (wid == 0) {
        int t = (lane < 16) ? wtot[lane] : 0;
#pragma unroll
        for (int o = 1; o < 16; o <<= 1) {
            int u = __shfl_up_sync(~0u, t, o);
            if (lane >= o) t += u;
        }
        if (lane < 16) wtot[lane] = t;
    }
    __syncthreads();
    int base = (wid > 0) ? wtot[wid - 1] : 0;
    int inclv = x + base;
    if (i < N) incl[i] = inclv;
    if (threadIdx.x == SCAN_B - 1) bsum[blockIdx.x] = inclv;
}

__global__ void scan2(int* __restrict__ bsum, int NB) {
    int i = threadIdx.x;
    int lane = i & 31, wid = i >> 5;
    int v = (i < NB) ? bsum[i] : 0;
    int x = v;
#pragma unroll
    for (int o = 1; o < 32; o <<= 1) {
        int t = __shfl_up_sync(~0u, x, o);
        if (lane >= o) x += t;
    }
    __shared__ int wtot[32];
    if (lane == 31) wtot[wid] = x;
    __syncthreads();
    if (wid == 0) {
        int t = wtot[lane];
#pragma unroll
        for (int o = 1; o < 32; o <<= 1) {
            int u = __shfl_up_sync(~0u, t, o);
            if (lane >= o) t += u;
        }
        wtot[lane] = t;
    }
    __syncthreads();
    int base = (wid > 0) ? wtot[wid - 1] : 0;
    if (i < NB) bsum[i] = x + base - v;
}

__global__ void scan3(int* __restrict__ cnt_cursor, int* __restrict__ off,
                      const int* __restrict__ bsum, float* __restrict__ dinv,
                      int N, int E) {
    int i = blockIdx.x * SCAN_B + threadIdx.x;
    if (i >= N) return;
    int c = cnt_cursor[i];
    int excl = off[i] - c + bsum[blockIdx.x];
    off[i] = excl;
    cnt_cursor[i] = excl;
    if (dinv) dinv[i] = rsqrtf((float)c + 1.0f);
    if (i == N - 1) off[N] = E;
}

__global__ void fill_csr(const int* __restrict__ src, const int* __restrict__ dst,
                         int* __restrict__ cursor, int* __restrict__ csrc, int E) {
    int e = blockIdx.x * blockDim.x + threadIdx.x;
    if (e >= E) return;
    int d = dst[e];
    int p = atomicAdd(cursor + d, 1);
    csrc[p] = src[e];
}

// warp per dst node: GCN gather + finalize (4 rows per iteration for MLP; validated)
__global__ void gcn_csr(const int* __restrict__ off, const int* __restrict__ csrc,
                        const float* __restrict__ dinv, const __nv_bfloat16* __restrict__ xw,
                        const float* __restrict__ xb, const float* __restrict__ bg,
                        float* __restrict__ out, int N) {
    int gt = blockIdx.x * blockDim.x + threadIdx.x;
    int n = gt >> 5, lane = gt & 31;
    if (n >= N) return;
    int o0 = off[n], o1 = off[n + 1];
    float a0 = 0.f, a1 = 0.f, a2 = 0.f, a3 = 0.f;
    for (int base = o0; base < o1; base += 32) {
        int eidx = base + lane;
        bool v = eidx < o1;
        int s_l = v ? csrc[eidx] : 0;
        float ds_l = v ? dinv[s_l] : 0.f;
        int cntc = min(32, o1 - base);
        int j = 0;
        for (; j + 3 < cntc; j += 4) {
            int sa = __shfl_sync(~0u, s_l, j);
            int sb = __shfl_sync(~0u, s_l, j + 1);
            int sc = __shfl_sync(~0u, s_l, j + 2);
            int sd = __shfl_sync(~0u, s_l, j + 3);
            float da = __shfl_sync(~0u, ds_l, j);
            float db = __shfl_sync(~0u, ds_l, j + 1);
            float dc = __shfl_sync(~0u, ds_l, j + 2);
            float dd2 = __shfl_sync(~0u, ds_l, j + 3);
            uint2 ra = *(const uint2*)(xw + (size_t)sa * 128 + lane * 4);
            uint2 rb = *(const uint2*)(xw + (size_t)sb * 128 + lane * 4);
            uint2 rc = *(const uint2*)(xw + (size_t)sc * 128 + lane * 4);
            uint2 rd = *(const uint2*)(xw + (size_t)sd * 128 + lane * 4);
            float2 fa0 = __bfloat1622float2(*(const __nv_bfloat162*)&ra.x);
            float2 fa1 = __bfloat1622float2(*(const __nv_bfloat162*)&ra.y);
            float2 fb0 = __bfloat1622float2(*(const __nv_bfloat162*)&rb.x);
            float2 fb1 = __bfloat1622float2(*(const __nv_bfloat162*)&rb.y);
            float2 fc0 = __bfloat1622float2(*(const __nv_bfloat162*)&rc.x);
            float2 fc1 = __bfloat1622float2(*(const __nv_bfloat162*)&rc.y);
            float2 fd0 = __bfloat1622float2(*(const __nv_bfloat162*)&rd.x);
            float2 fd1 = __bfloat1622float2(*(const __nv_bfloat162*)&rd.y);
            a0 += da * fa0.x + db * fb0.x + dc * fc0.x + dd2 * fd0.x;
            a1 += da * fa0.y + db * fb0.y + dc * fc0.y + dd2 * fd0.y;
            a2 += da * fa1.x + db * fb1.x + dc * fc1.x + dd2 * fd1.x;
            a3 += da * fa1.y + db * fb1.y + dc * fc1.y + dd2 * fd1.y;
        }
        for (; j < cntc; j++) {
            int s = __shfl_sync(~0u, s_l, j);
            float ds = __shfl_sync(~0u, ds_l, j);
            uint2 raw = *(const uint2*)(xw + (size_t)s * 128 + lane * 4);
            float2 f0 = __bfloat1622float2(*(const __nv_bfloat162*)&raw.x);
            float2 f1 = __bfloat1622float2(*(const __nv_bfloat162*)&raw.y);
            a0 += ds * f0.x; a1 += ds * f0.y; a2 += ds * f1.x; a3 += ds * f1.y;
        }
    }
    float dn = dinv[n];
    float dd = dn * dn;
    float4 xv = *(const float4*)(xb + (size_t)n * 128 + lane * 4);
    uint2 rw = *(const uint2*)(xw + (size_t)n * 128 + lane * 4);
    float2 s0 = __bfloat1622float2(*(const __nv_bfloat162*)&rw.x);
    float2 s1 = __bfloat1622float2(*(const __nv_bfloat162*)&rw.y);
    float4 bv = *(const float4*)(bg + lane * 4);
    float4 o;
    o.x = xv.x + 0.2f * (dn * a0 + dd * s0.x + bv.x);
    o.y = xv.y + 0.2f * (dn * a1 + dd * s0.y + bv.y);
    o.z = xv.z + 0.2f * (dn * a2 + dd * s1.x + bv.z);
    o.w = xv.w + 0.2f * (dn * a3 + dd * s1.y + bv.w);
    *(float4*)(out + (size_t)n * 128 + lane * 4) = o;
}

// ---------------- launcher (single stream, R7 structure) ----------------
static inline unsigned cdivu(long a, long b) { return (unsigned)((a + b - 1) / b); }

extern "C" void kernel_launch(void* const* d_in, const int* in_sizes, int n_in,
                              void* d_out, int out_size) {
    const float* xb  = (const float*)d_in[0];
    const float* xc  = (const float*)d_in[1];
    const float* xt  = (const float*)d_in[2];
    const float* Ws1 = (const float*)d_in[3];
    const float* Wd1 = (const float*)d_in[4];
    const float* as1 = (const float*)d_in[5];
    const float* ad1 = (const float*)d_in[6];
    const float* b1  = (const float*)d_in[7];
    const float* Ws2 = (const float*)d_in[8];
    const float* Wd2 = (const float*)d_in[9];
    const float* as2 = (const float*)d_in[10];
    const float* ad2 = (const float*)d_in[11];
    const float* b2  = (const float*)d_in[12];
    const float* Wg  = (const float*)d_in[13];
    const float* bg  = (const float*)d_in[14];
    const int* b2c_src = (const int*)d_in[15];
    const int* b2c_dst = (const int*)d_in[16];
    const int* c2t_src = (const int*)d_in[17];
    const int* c2t_dst = (const int*)d_in[18];
    const int* adj_src = (const int*)d_in[19];
    const int* adj_dst = (const int*)d_in[20];

    int Nb = in_sizes[0] / 128, Nc = in_sizes[1] / 128, Nt = in_sizes[2] / 128;
    int Ebc = in_sizes[15], Ect = in_sizes[17], Eadj = in_sizes[19];

    float* out   = (float*)d_out;
    float* out_b = out;
    float* out_c = out + (size_t)Nb * 128;
    float* out_t = out_c + (size_t)Nc * 128;

    void* p;
    cudaGetSymbolAddress(&p, g_hs);    __nv_bfloat16* hs = (__nv_bfloat16*)p;
    cudaGetSymbolAddress(&p, g_xw);    __nv_bfloat16* xw = (__nv_bfloat16*)p;
    cudaGetSymbolAddress(&p, g_es);    float* es   = (float*)p;
    cudaGetSymbolAddress(&p, g_ed);    float* ed   = (float*)p;
    cudaGetSymbolAddress(&p, g_edt);   float* edt  = (float*)p;
    cudaGetSymbolAddress(&p, g_sb);    float* sbuf = (float*)p;
    cudaGetSymbolAddress(&p, g_wb);    float* wbuf = (float*)p;
    cudaGetSymbolAddress(&p, g_dinv);  float* dinv = (float*)p;
    cudaGetSymbolAddress(&p, g_cntc);  int* cntc = (int*)p;
    cudaGetSymbolAddress(&p, g_offc);  int* offc = (int*)p;
    cudaGetSymbolAddress(&p, g_cntb);  int* cntb = (int*)p;
    cudaGetSymbolAddress(&p, g_offb);  int* offb = (int*)p;
    cudaGetSymbolAddress(&p, g_csrc_c); int* csrcc = (int*)p;
    cudaGetSymbolAddress(&p, g_csrc_b); int* csrcb = (int*)p;
    cudaGetSymbolAddress(&p, g_bsum);  int* bsum = (int*)p;
    cudaGetSymbolAddress(&p, g_v2a);   float* v2a = (float*)p;
    cudaGetSymbolAddress(&p, g_v2b);   float* v2b = (float*)p;
    cudaGetSymbolAddress(&p, g_wt1);   float* wt1 = (float*)p;
    cudaGetSymbolAddress(&p, g_wt2);   float* wt2 = (float*)p;
    cudaGetSymbolAddress(&p, g_wtg);   float* wtg = (float*)p;

    cudaFuncSetAttribute(gemm_mma, cudaFuncAttributeMaxDynamicSharedMemorySize, MMA_SMEM);
    cudaFuncSetAttribute(gemm_dual, cudaFuncAttributeMaxDynamicSharedMemorySize, MMA_SMEM);

    // ---- critical path, single stream ----
    transpose_w3<<<dim3(4, 4, 3), dim3(32, 8)>>>(Ws1, Ws2, Wg, wt1, wt2, wtg);
    gemm_dual<<<cdivu(Nb, 128), 256, MMA_SMEM>>>(xb, wt1, wtg, hs, xw, Nb, es, as1);

    precompute_v2<<<2, 128>>>(Wd1, ad1, Wd2, ad2, v2a, v2b);
    node_alpha<<<cdivu((long)Nc * 32, 256), 256>>>(xc, v2a, ed, Nc);
    node_alpha<<<cdivu((long)Nt * 32, 256), 256>>>(xt, v2b, edt, Nt);
    cudaMemsetAsync(sbuf, 0, (size_t)Nt * 4 * sizeof(float), 0);

    // GAT1 CSR build (over Nc)
    int NCb = cdivu(Nc, SCAN_B);
    cudaMemsetAsync(cntc, 0, (size_t)Nc * sizeof(int), 0);
    count_dst<<<cdivu(Ebc, 256), 256>>>(b2c_dst, cntc, Ebc);
    scan1<<<NCb, SCAN_B>>>(cntc, offc, bsum, Nc);
    scan2<<<1, 1024>>>(bsum, NCb);
    scan3<<<NCb, SCAN_B>>>(cntc, offc, bsum, (float*)nullptr, Nc, Ebc);
    edge_w_fill<<<cdivu(Ebc, 256), 256>>>(es, ed, b2c_src, b2c_dst, cntc, csrcc, wbuf, Ebc);
    gat_csr<<<cdivu((long)Nc * 32, 256), 256>>>(offc, csrcc, wbuf, hs, xc, b1, out_c, Nc);

    // GAT2: cable -> transformer (COO, small)
    gemm_mma<<<cdivu(Nc, 128), 256, MMA_SMEM>>>(out_c, wt2, hs, Nc, es, as2);
    edge_w<<<cdivu(Ect, 256), 256>>>(es, edt, c2t_src, c2t_dst, wbuf, sbuf, Ect);
    init_half_bias<<<cdivu((long)Nt * 32, 256), 256>>>(xt, b2, out_t, Nt);
    edge_aggr<<<cdivu((long)Ect * 32, 256), 256>>>(wbuf, sbuf, c2t_src, c2t_dst, hs, out_t, Ect);

    // GCN CSR build (over Nb) + finalize
    int NBb = cdivu(Nb, SCAN_B);
    cudaMemsetAsync(cntb, 0, (size_t)Nb * sizeof(int), 0);
    count_dst<<<cdivu(Eadj, 256), 256>>>(adj_dst, cntb, Eadj);
    scan1<<<NBb, SCAN_B>>>(cntb, offb, bsum, Nb);
    scan2<<<1, 1024>>>(bsum, NBb);
    scan3<<<NBb, SCAN_B>>>(cntb, offb, bsum, dinv, Nb, Eadj);
    fill_csr<<<cdivu(Eadj, 256), 256>>>(adj_src, adj_dst, cntb, csrcb, Eadj);
    gcn_csr<<<cdivu((long)Nb * 32, 256), 256>>>(offb, csrcb, dinv, xw, xb, bg, out_b, Nb);
}

// round 16
// speedup vs baseline: 1.1169x; 1.1169x over previous
#include <cuda_runtime.h>
#include <cuda_bf16.h>
#include <cstdint>

// ---------------- scratch (device globals; no allocations allowed) ----------------
#define MAXNB 200000
#define MAXNC 20000
#define MAXNT 2000
#define MAXE_GAT 200000
#define MAXE_ADJ 1600000
#define SCAN_B 512

__device__ __nv_bfloat16 g_hs[(size_t)MAXNB * 128];  // hs1, later hs2
__device__ __nv_bfloat16 g_xw[(size_t)MAXNB * 128];  // GCN xw
__device__ float g_es[(size_t)MAXNB * 4];
__device__ float g_ed[(size_t)MAXNC * 4];
__device__ float g_edt[(size_t)MAXNT * 4];
__device__ float g_sb[(size_t)MAXNT * 4];
__device__ float g_wb[(size_t)MAXE_GAT * 4];
__device__ float g_dinv[MAXNB];
__device__ int g_cntc[MAXNC];
__device__ int g_offc[MAXNC + 1];
__device__ int g_cntb[MAXNB];
__device__ int g_offb[MAXNB + 1];
__device__ int g_csrc_c[MAXE_GAT];
__device__ int g_csrc_b[MAXE_ADJ];
__device__ int g_bsum[1024];
__device__ float g_v2a[128 * 4];
__device__ float g_v2b[128 * 4];
__device__ float g_wt1[128 * 128];
__device__ float g_wt2[128 * 128];
__device__ float g_wtg[128 * 128];

static __device__ __forceinline__ void red_add_v4(float* addr, float x, float y, float z, float w) {
    asm volatile("red.global.add.v4.f32 [%0], {%1,%2,%3,%4};"
                 :: "l"(addr), "f"(x), "f"(y), "f"(z), "f"(w) : "memory");
}

static __device__ __forceinline__ unsigned bf2pack(float c0, float c1) {
    unsigned r;
    asm("cvt.rn.bf16x2.f32 %0, %1, %2;" : "=r"(r) : "f"(c1), "f"(c0));
    return r;
}

static __device__ __forceinline__ uint32_t tf32r(float v) {
    uint32_t r;
    asm("cvt.rna.tf32.f32 %0, %1;" : "=r"(r) : "f"(v));
    return r;
}

// 3 weights transposed ([n][k]) + tf32-rounded, selected by blockIdx.z
__global__ void transpose_w3(const float* __restrict__ W0, const float* __restrict__ W1,
                             const float* __restrict__ W2, float* __restrict__ T0,
                             float* __restrict__ T1, float* __restrict__ T2) {
    const float* W = blockIdx.z == 0 ? W0 : (blockIdx.z == 1 ? W1 : W2);
    float* T = blockIdx.z == 0 ? T0 : (blockIdx.z == 1 ? T1 : T2);
    __shared__ float t[32][33];
    int bx = blockIdx.x * 32, by = blockIdx.y * 32;
#pragma unroll
    for (int j = 0; j < 32; j += 8)
        t[threadIdx.y + j][threadIdx.x] =
            __uint_as_float(tf32r(W[(size_t)(by + threadIdx.y + j) * 128 + bx + threadIdx.x]));
    __syncthreads();
#pragma unroll
    for (int j = 0; j < 32; j += 8)
        T[(size_t)(bx + threadIdx.y + j) * 128 + by + threadIdx.x] = t[threadIdx.x][threadIdx.y + j];
}

__global__ void precompute_v2(const float* __restrict__ Wd1, const float* __restrict__ ad1,
                              const float* __restrict__ Wd2, const float* __restrict__ ad2,
                              float* __restrict__ Va, float* __restrict__ Vb) {
    const float* W = blockIdx.x == 0 ? Wd1 : Wd2;
    const float* a = blockIdx.x == 0 ? ad1 : ad2;
    float* V = blockIdx.x == 0 ? Va : Vb;
    int d = threadIdx.x;
    float s[4] = {0.f, 0.f, 0.f, 0.f};
#pragma unroll
    for (int h = 0; h < 4; h++)
        for (int c = 0; c < 32; c++)
            s[h] += W[d * 128 + h * 32 + c] * a[h * 32 + c];
    ((float4*)V)[d] = make_float4(s[0], s[1], s[2], s[3]);
}

// ---------------- tf32 mma.sync GEMMs (32-row x 64-col warp tiles; R11 config) ------
#define AP 132
#define MMA_SMEM ((128 * AP * 2) * 4)

static __device__ __forceinline__ void mma_loop32(const uint32_t* __restrict__ Asu,
                                                  const uint32_t* __restrict__ Wsu,
                                                  int ar0, int bbase, int t,
                                                  float acc[2][8][4]) {
    int ar1 = ar0 + 8 * AP, ar2 = ar0 + 16 * AP, ar3 = ar0 + 24 * AP;
#pragma unroll 2
    for (int ks = 0; ks < 16; ks++) {
        int k0 = ks * 8;
        uint32_t a00 = Asu[ar0 + k0 + t];
        uint32_t a01 = Asu[ar1 + k0 + t];
        uint32_t a02 = Asu[ar0 + k0 + t + 4];
        uint32_t a03 = Asu[ar1 + k0 + t + 4];
        uint32_t a10 = Asu[ar2 + k0 + t];
        uint32_t a11 = Asu[ar3 + k0 + t];
        uint32_t a12 = Asu[ar2 + k0 + t + 4];
        uint32_t a13 = Asu[ar3 + k0 + t + 4];
#pragma unroll
        for (int nt = 0; nt < 8; nt++) {
            uint32_t b0 = Wsu[bbase + nt * 8 * AP + k0 + t];
            uint32_t b1 = Wsu[bbase + nt * 8 * AP + k0 + t + 4];
            asm("mma.sync.aligned.m16n8k8.row.col.f32.tf32.tf32.f32 "
                "{%0,%1,%2,%3}, {%4,%5,%6,%7}, {%8,%9}, {%0,%1,%2,%3};"
                : "+f"(acc[0][nt][0]), "+f"(acc[0][nt][1]), "+f"(acc[0][nt][2]), "+f"(acc[0][nt][3])
                : "r"(a00), "r"(a01), "r"(a02), "r"(a03), "r"(b0), "r"(b1));
            asm("mma.sync.aligned.m16n8k8.row.col.f32.tf32.tf32.f32 "
                "{%0,%1,%2,%3}, {%4,%5,%6,%7}, {%8,%9}, {%0,%1,%2,%3};"
                : "+f"(acc[1][nt][0]), "+f"(acc[1][nt][1]), "+f"(acc[1][nt][2]), "+f"(acc[1][nt][3])
                : "r"(a10), "r"(a11), "r"(a12), "r"(a13), "r"(b0), "r"(b1));
        }
    }
}

static __device__ __forceinline__ void mma_epilogue32(float acc[2][8][4], __nv_bfloat16* C,
                                                      int M, int brow, int wr, int wc,
                                                      int g, int t, float* es_out,
                                                      const float* a_s) {
    int grow[4];
    grow[0] = brow + wr * 32 + g;
    grow[1] = grow[0] + 8;
    grow[2] = grow[0] + 16;
    grow[3] = grow[0] + 24;
    bool okr[4];
#pragma unroll
    for (int s = 0; s < 4; s++) okr[s] = grow[s] < M;
    bool do_es = es_out != nullptr;
    float sv[4][2] = {{0.f, 0.f}, {0.f, 0.f}, {0.f, 0.f}, {0.f, 0.f}};
#pragma unroll
    for (int mg = 0; mg < 2; mg++) {
#pragma unroll
        for (int nt = 0; nt < 8; nt++) {
            float c0 = acc[mg][nt][0], c1 = acc[mg][nt][1];
            float c2 = acc[mg][nt][2], c3 = acc[mg][nt][3];
            int col = wc * 64 + nt * 8 + 2 * t;
            if (okr[mg * 2])
                *(unsigned*)(C + (size_t)grow[mg * 2] * 128 + col) = bf2pack(c0, c1);
            if (okr[mg * 2 + 1])
                *(unsigned*)(C + (size_t)grow[mg * 2 + 1] * 128 + col) = bf2pack(c2, c3);
            if (do_es) {
                int hl = nt >> 2;
                int cb = (wc * 2 + hl) * 32 + (nt & 3) * 8 + 2 * t;
                float av0 = __ldg(a_s + cb), av1 = __ldg(a_s + cb + 1);
                sv[mg * 2][hl]     += c0 * av0 + c1 * av1;
                sv[mg * 2 + 1][hl] += c2 * av0 + c3 * av1;
            }
        }
    }
    if (do_es) {
#pragma unroll
        for (int s = 0; s < 4; s++) {
#pragma unroll
            for (int hl = 0; hl < 2; hl++) {
                sv[s][hl] += __shfl_down_sync(~0u, sv[s][hl], 1);
                sv[s][hl] += __shfl_down_sync(~0u, sv[s][hl], 2);
            }
        }
        if (t == 0) {
#pragma unroll
            for (int s = 0; s < 4; s++) {
                if (okr[s])
                    *(float2*)(es_out + (size_t)grow[s] * 4 + wc * 2) =
                        make_float2(sv[s][0], sv[s][1]);
            }
        }
    }
}

__global__ void __launch_bounds__(256, 1)
gemm_mma(const float* __restrict__ A, const float* __restrict__ Wt,
         __nv_bfloat16* __restrict__ C, int M,
         float* __restrict__ es_out, const float* __restrict__ a_s) {
    extern __shared__ float smem[];
    float* As = smem;
    float* Ws = smem + 128 * AP;
    int tid = threadIdx.x;
    int brow = blockIdx.x * 128;
    {
        int row = tid & 127;
        int k0 = (tid >> 7) * 64;
        int grow = brow + row;
        bool ok = grow < M;
        const float4* Ar = (const float4*)(A + (size_t)grow * 128 + k0);
        const float4* Wr = (const float4*)(Wt + (size_t)row * 128 + k0);
#pragma unroll
        for (int i = 0; i < 16; i++) {
            float4 v = make_float4(0.f, 0.f, 0.f, 0.f);
            if (ok) v = Ar[i];
            uint4 tv;
            tv.x = tf32r(v.x); tv.y = tf32r(v.y); tv.z = tf32r(v.z); tv.w = tf32r(v.w);
            *(uint4*)(As + row * AP + k0 + i * 4) = tv;
            *(float4*)(Ws + row * AP + k0 + i * 4) = Wr[i];
        }
    }
    __syncthreads();

    int wid = tid >> 5, lane = tid & 31;
    int g = lane >> 2, t = lane & 3;
    int wr = wid >> 1, wc = wid & 1;
    float acc[2][8][4];
#pragma unroll
    for (int mg = 0; mg < 2; mg++)
#pragma unroll
        for (int nt = 0; nt < 8; nt++)
#pragma unroll
            for (int j = 0; j < 4; j++) acc[mg][nt][j] = 0.f;
    mma_loop32((const uint32_t*)As, (const uint32_t*)Ws,
               (wr * 32 + g) * AP, (wc * 64 + g) * AP, t, acc);
    mma_epilogue32(acc, C, M, brow, wr, wc, g, t, es_out, a_s);
}

__global__ void __launch_bounds__(256, 1)
gemm_dual(const float* __restrict__ A, const float* __restrict__ Wt0,
          const float* __restrict__ Wt1, __nv_bfloat16* __restrict__ C0,
          __nv_bfloat16* __restrict__ C1, int M,
          float* __restrict__ es_out, const float* __restrict__ a_s) {
    extern __shared__ float smem[];
    float* As = smem;
    float* Ws = smem + 128 * AP;
    int tid = threadIdx.x;
    int brow = blockIdx.x * 128;
    int row = tid & 127;
    int k0 = (tid >> 7) * 64;
    {
        int grow = brow + row;
        bool ok = grow < M;
        const float4* Ar = (const float4*)(A + (size_t)grow * 128 + k0);
#pragma unroll
        for (int i = 0; i < 16; i++) {
            float4 v = make_float4(0.f, 0.f, 0.f, 0.f);
            if (ok) v = Ar[i];
            uint4 tv;
            tv.x = tf32r(v.x); tv.y = tf32r(v.y); tv.z = tf32r(v.z); tv.w = tf32r(v.w);
            *(uint4*)(As + row * AP + k0 + i * 4) = tv;
        }
    }

    int wid = tid >> 5, lane = tid & 31;
    int g = lane >> 2, t = lane & 3;
    int wr = wid >> 1, wc = wid & 1;
    int ar0 = (wr * 32 + g) * AP;
    int bbase = (wc * 64 + g) * AP;

#pragma unroll
    for (int p = 0; p < 2; p++) {
        const float* Wt = p == 0 ? Wt0 : Wt1;
        {
            const float4* Wr = (const float4*)(Wt + (size_t)row * 128 + k0);
#pragma unroll
            for (int i = 0; i < 16; i++)
                *(float4*)(Ws + row * AP + k0 + i * 4) = Wr[i];
        }
        __syncthreads();
        float acc[2][8][4];
#pragma unroll
        for (int mg = 0; mg < 2; mg++)
#pragma unroll
            for (int nt = 0; nt < 8; nt++)
#pragma unroll
                for (int j = 0; j < 4; j++) acc[mg][nt][j] = 0.f;
        mma_loop32((const uint32_t*)As, (const uint32_t*)Ws, ar0, bbase, t, acc);
        __syncthreads();  // safe to overwrite Ws next phase
        mma_epilogue32(acc, p == 0 ? C0 : C1, M, brow, wr, wc, g, t,
                       p == 0 ? es_out : (float*)nullptr, a_s);
    }
}

// out[n,h] = x[n,:] @ V[:,h]   (warp per node)
__global__ void node_alpha(const float* __restrict__ X, const float* __restrict__ V,
                           float* __restrict__ out, int N) {
    int gt = blockIdx.x * blockDim.x + threadIdx.x;
    int n = gt >> 5, lane = gt & 31;
    if (n >= N) return;
    float4 x = ((const float4*)(X + (size_t)n * 128))[lane];
    const float4* Vv = (const float4*)V;
    float xv[4] = {x.x, x.y, x.z, x.w};
    float s0 = 0.f, s1 = 0.f, s2 = 0.f, s3 = 0.f;
#pragma unroll
    for (int j = 0; j < 4; j++) {
        float4 v = Vv[lane * 4 + j];
        s0 += xv[j] * v.x; s1 += xv[j] * v.y;
        s2 += xv[j] * v.z; s3 += xv[j] * v.w;
    }
#pragma unroll
    for (int off = 16; off; off >>= 1) {
        s0 += __shfl_down_sync(~0u, s0, off);
        s1 += __shfl_down_sync(~0u, s1, off);
        s2 += __shfl_down_sync(~0u, s2, off);
        s3 += __shfl_down_sync(~0u, s3, off);
    }
    if (lane == 0) ((float4*)out)[n] = make_float4(s0, s1, s2, s3);
}

static __device__ __forceinline__ float4 edge_w4(const float* es, const float* ed, int s, int d) {
    float4 a = ((const float4*)es)[s];
    float4 b = ((const float4*)ed)[d];
    float t0 = a.x + b.x, t1 = a.y + b.y, t2 = a.z + b.z, t3 = a.w + b.w;
    t0 = t0 > 0.f ? t0 : 0.2f * t0;
    t1 = t1 > 0.f ? t1 : 0.2f * t1;
    t2 = t2 > 0.f ? t2 : 0.2f * t2;
    t3 = t3 > 0.f ? t3 : 0.2f * t3;
    return make_float4(__expf(t0), __expf(t1), __expf(t2), __expf(t3));
}

// COO edge_w for GAT2 (small)
__global__ void edge_w(const float* __restrict__ es, const float* __restrict__ ed,
                       const int* __restrict__ src, const int* __restrict__ dst,
                       float* __restrict__ w, float* __restrict__ ssum, int E) {
    int e = blockIdx.x * blockDim.x + threadIdx.x;
    if (e >= E) return;
    int s = src[e], d = dst[e];
    float4 wv = edge_w4(es, ed, s, d);
    ((float4*)w)[e] = wv;
    red_add_v4(ssum + (size_t)d * 4, wv.x, wv.y, wv.z, wv.w);
}

// CSR edge_w + fill for GAT1
__global__ void edge_w_fill(const float* __restrict__ es, const float* __restrict__ ed,
                            const int* __restrict__ src, const int* __restrict__ dst,
                            int* __restrict__ cursor, int* __restrict__ csrc,
                            float* __restrict__ w, int E) {
    int e = blockIdx.x * blockDim.x + threadIdx.x;
    if (e >= E) return;
    int s = src[e], d = dst[e];
    float4 wv = edge_w4(es, ed, s, d);
    int p = atomicAdd(cursor + d, 1);
    csrc[p] = s;
    ((float4*)w)[p] = wv;
}

// warp per dst node: softmax-sum + gather + finalize
// 2 rows per iteration (R13 MLP); weights loaded directly per-head (no shuffles).
__global__ void gat_csr(const int* __restrict__ off, const int* __restrict__ csrc,
                        const float* __restrict__ wbuf, const __nv_bfloat16* __restrict__ hs,
                        const float* __restrict__ xdst, const float* __restrict__ bias,
                        float* __restrict__ out, int N) {
    int gt = blockIdx.x * blockDim.x + threadIdx.x;
    int n = gt >> 5, lane = gt & 31;
    if (n >= N) return;
    int o0 = off[n], o1 = off[n + 1];
    float sw0 = 0.f, sw1 = 0.f, sw2 = 0.f, sw3 = 0.f;
    for (int e = o0 + lane; e < o1; e += 32) {
        float4 w = ((const float4*)wbuf)[e];
        sw0 += w.x; sw1 += w.y; sw2 += w.z; sw3 += w.w;
    }
#pragma unroll
    for (int o = 16; o; o >>= 1) {
        sw0 += __shfl_xor_sync(~0u, sw0, o);
        sw1 += __shfl_xor_sync(~0u, sw1, o);
        sw2 += __shfl_xor_sync(~0u, sw2, o);
        sw3 += __shfl_xor_sync(~0u, sw3, o);
    }
    int h = lane >> 3;
    float stot = (h < 2) ? (h == 0 ? sw0 : sw1) : (h == 2 ? sw2 : sw3);
    float kinv = 0.5f / (stot + 1e-16f);
    float a0 = 0.f, a1 = 0.f, a2 = 0.f, a3 = 0.f;
    for (int base = o0; base < o1; base += 32) {
        int eidx = base + lane;
        bool v = eidx < o1;
        int s_l = v ? csrc[eidx] : 0;
        int cntc = min(32, o1 - base);
        int j = 0;
        for (; j + 1 < cntc; j += 2) {
            int sa = __shfl_sync(~0u, s_l, j);
            int sb = __shfl_sync(~0u, s_l, j + 1);
            // direct per-head weight loads (lane's own head); L2-hot, 16B span per edge
            float ka = wbuf[(size_t)(base + j) * 4 + h];
            float kb = wbuf[(size_t)(base + j + 1) * 4 + h];
            uint2 ra = *(const uint2*)(hs + (size_t)sa * 128 + lane * 4);
            uint2 rb = *(const uint2*)(hs + (size_t)sb * 128 + lane * 4);
            ka *= kinv; kb *= kinv;
            float2 fa0 = __bfloat1622float2(*(const __nv_bfloat162*)&ra.x);
            float2 fa1 = __bfloat1622float2(*(const __nv_bfloat162*)&ra.y);
            float2 fb0 = __bfloat1622float2(*(const __nv_bfloat162*)&rb.x);
            float2 fb1 = __bfloat1622float2(*(const __nv_bfloat162*)&rb.y);
            a0 += ka * fa0.x + kb * fb0.x;
            a1 += ka * fa0.y + kb * fb0.y;
            a2 += ka * fa1.x + kb * fb1.x;
            a3 += ka * fa1.y + kb * fb1.y;
        }
        if (j < cntc) {
            int s = __shfl_sync(~0u, s_l, j);
            float k = wbuf[(size_t)(base + j) * 4 + h] * kinv;
            uint2 raw = *(const uint2*)(hs + (size_t)s * 128 + lane * 4);
            float2 f0 = __bfloat1622float2(*(const __nv_bfloat162*)&raw.x);
            float2 f1 = __bfloat1622float2(*(const __nv_bfloat162*)&raw.y);
            a0 += k * f0.x; a1 += k * f0.y; a2 += k * f1.x; a3 += k * f1.y;
        }
    }
    float4 xv = *(const float4*)(xdst + (size_t)n * 128 + lane * 4);
    float4 bv = *(const float4*)(bias + lane * 4);
    float4 o;
    o.x = xv.x + 0.5f * bv.x + a0;
    o.y = xv.y + 0.5f * bv.y + a1;
    o.z = xv.z + 0.5f * bv.z + a2;
    o.w = xv.w + 0.5f * bv.w + a3;
    *(float4*)(out + (size_t)n * 128 + lane * 4) = o;
}

// warp per edge: out[dst] += 0.5 * alpha * hs_bf16[src]  (COO, GAT2)
__global__ void edge_aggr(const float* __restrict__ w, const float* __restrict__ ssum,
                          const int* __restrict__ src, const int* __restrict__ dst,
                          const __nv_bfloat16* __restrict__ hs, float* __restrict__ out, int E) {
    int gt = blockIdx.x * blockDim.x + threadIdx.x;
    int e = gt >> 5, lane = gt & 31;
    if (e >= E) return;
    int s = src[e], d = dst[e];
    int h = lane >> 3;
    float alpha = w[(size_t)e * 4 + h] / (ssum[(size_t)d * 4 + h] + 1e-16f);
    float k = 0.5f * alpha;
    uint2 raw = *(const uint2*)(hs + (size_t)s * 128 + lane * 4);
    float2 f0 = __bfloat1622float2(*(const __nv_bfloat162*)&raw.x);
    float2 f1 = __bfloat1622float2(*(const __nv_bfloat162*)&raw.y);
    red_add_v4(out + (size_t)d * 128 + lane * 4, k * f0.x, k * f0.y, k * f1.x, k * f1.y);
}

// out[n,c] = x[n,c] + 0.5*b[c]
__global__ void init_half_bias(const float* __restrict__ x, const float* __restrict__ b,
                               float* __restrict__ out, int N) {
    int i = blockIdx.x * blockDim.x + threadIdx.x;
    if (i >= N * 32) return;
    float4 xv = ((const float4*)x)[i];
    float4 bv = ((const float4*)b)[i & 31];
    ((float4*)out)[i] = make_float4(xv.x + 0.5f * bv.x, xv.y + 0.5f * bv.y,
                                    xv.z + 0.5f * bv.z, xv.w + 0.5f * bv.w);
}

// ---------------- CSR build ----------------
__global__ void count_dst(const int* __restrict__ dst, int* __restrict__ cnt, int E) {
    int e = blockIdx.x * blockDim.x + threadIdx.x;
    if (e < E) atomicAdd(cnt + dst[e], 1);
}

__global__ void scan1(const int* __restrict__ cnt, int* __restrict__ incl,
                      int* __restrict__ bsum, int N) {
    int i = blockIdx.x * SCAN_B + threadIdx.x;
    int lane = threadIdx.x & 31, wid = threadIdx.x >> 5;
    int v = (i < N) ? cnt[i] : 0;
    int x = v;
#pragma unroll
    for (int o = 1; o < 32; o <<= 1) {
        int t = __shfl_up_sync(~0u, x, o);
        if (lane >= o) x += t;
    }
    __shared__ int wtot[16];
    if (lane == 31) wtot[wid] = x;
    __syncthreads();
    if (wid == 0) {
        int t = (lane < 16) ? wtot[lane] : 0;
#pragma unroll
        for (int o = 1; o < 16; o <<= 1) {
            int u = __shfl_up_sync(~0u, t, o);
            if (lane >= o) t += u;
        }
        if (lane < 16) wtot[lane] = t;
    }
    __syncthreads();
    int base = (wid > 0) ? wtot[wid - 1] : 0;
    int inclv = x + base;
    if (i < N) incl[i] = inclv;
    if (threadIdx.x == SCAN_B - 1) bsum[blockIdx.x] = inclv;
}

__global__ void scan2(int* __restrict__ bsum, int NB) {
    int i = threadIdx.x;
    int lane = i & 31, wid = i >> 5;
    int v = (i < NB) ? bsum[i] : 0;
    int x = v;
#pragma unroll
    for (int o = 1; o < 32; o <<= 1) {
        int t = __shfl_up_sync(~0u, x, o);
        if (lane >= o) x += t;
    }
    __shared__ int wtot[32];
    if (lane == 31) wtot[wid] = x;
    __syncthreads();
    if (wid == 0) {
        int t = wtot[lane];
#pragma unroll
        for (int o = 1; o < 32; o <<= 1) {
            int u = __shfl_up_sync(~0u, t, o);
            if (lane >= o) t += u;
        }
        wtot[lane] = t;
    }
    __syncthreads();
    int base = (wid > 0) ? wtot[wid - 1] : 0;
    if (i < NB) bsum[i] = x + base - v;
}

__global__ void scan3(int* __restrict__ cnt_cursor, int* __restrict__ off,
                      const int* __restrict__ bsum, float* __restrict__ dinv,
                      int N, int E) {
    int i = blockIdx.x * SCAN_B + threadIdx.x;
    if (i >= N) return;
    int c = cnt_cursor[i];
    int excl = off[i] - c + bsum[blockIdx.x];
    off[i] = excl;
    cnt_cursor[i] = excl;
    if (dinv) dinv[i] = rsqrtf((float)c + 1.0f);
    if (i == N - 1) off[N] = E;
}

__global__ void fill_csr(const int* __restrict__ src, const int* __restrict__ dst,
                         int* __restrict__ cursor, int* __restrict__ csrc, int E) {
    int e = blockIdx.x * blockDim.x + threadIdx.x;
    if (e >= E) return;
    int d = dst[e];
    int p = atomicAdd(cursor + d, 1);
    csrc[p] = src[e];
}

// warp per dst node: GCN gather + finalize (2 rows per iteration; R13 validated)
__global__ void gcn_csr(const int* __restrict__ off, const int* __restrict__ csrc,
                        const float* __restrict__ dinv, const __nv_bfloat16* __restrict__ xw,
                        const float* __restrict__ xb, const float* __restrict__ bg,
                        float* __restrict__ out, int N) {
    int gt = blockIdx.x * blockDim.x + threadIdx.x;
    int n = gt >> 5, lane = gt & 31;
    if (n >= N) return;
    int o0 = off[n], o1 = off[n + 1];
    float a0 = 0.f, a1 = 0.f, a2 = 0.f, a3 = 0.f;
    for (int base = o0; base < o1; base += 32) {
        int eidx = base + lane;
        bool v = eidx < o1;
        int s_l = v ? csrc[eidx] : 0;
        float ds_l = v ? dinv[s_l] : 0.f;
        int cntc = min(32, o1 - base);
        int j = 0;
        for (; j + 1 < cntc; j += 2) {
            int sa = __shfl_sync(~0u, s_l, j);
            int sb = __shfl_sync(~0u, s_l, j + 1);
            float da = __shfl_sync(~0u, ds_l, j);
            float db = __shfl_sync(~0u, ds_l, j + 1);
            uint2 ra = *(const uint2*)(xw + (size_t)sa * 128 + lane * 4);
            uint2 rb = *(const uint2*)(xw + (size_t)sb * 128 + lane * 4);
            float2 fa0 = __bfloat1622float2(*(const __nv_bfloat162*)&ra.x);
            float2 fa1 = __bfloat1622float2(*(const __nv_bfloat162*)&ra.y);
            float2 fb0 = __bfloat1622float2(*(const __nv_bfloat162*)&rb.x);
            float2 fb1 = __bfloat1622float2(*(const __nv_bfloat162*)&rb.y);
            a0 += da * fa0.x + db * fb0.x;
            a1 += da * fa0.y + db * fb0.y;
            a2 += da * fa1.x + db * fb1.x;
            a3 += da * fa1.y + db * fb1.y;
        }
        if (j < cntc) {
            int s = __shfl_sync(~0u, s_l, j);
            float ds = __shfl_sync(~0u, ds_l, j);
            uint2 raw = *(const uint2*)(xw + (size_t)s * 128 + lane * 4);
            float2 f0 = __bfloat1622float2(*(const __nv_bfloat162*)&raw.x);
            float2 f1 = __bfloat1622float2(*(const __nv_bfloat162*)&raw.y);
            a0 += ds * f0.x; a1 += ds * f0.y; a2 += ds * f1.x; a3 += ds * f1.y;
        }
    }
    float dn = dinv[n];
    float dd = dn * dn;
    float4 xv = *(const float4*)(xb + (size_t)n * 128 + lane * 4);
    uint2 rw = *(const uint2*)(xw + (size_t)n * 128 + lane * 4);
    float2 s0 = __bfloat1622float2(*(const __nv_bfloat162*)&rw.x);
    float2 s1 = __bfloat1622float2(*(const __nv_bfloat162*)&rw.y);
    float4 bv = *(const float4*)(bg + lane * 4);
    float4 o;
    o.x = xv.x + 0.2f * (dn * a0 + dd * s0.x + bv.x);
    o.y = xv.y + 0.2f * (dn * a1 + dd * s0.y + bv.y);
    o.z = xv.z + 0.2f * (dn * a2 + dd * s1.x + bv.z);
    o.w = xv.w + 0.2f * (dn * a3 + dd * s1.y + bv.w);
    *(float4*)(out + (size_t)n * 128 + lane * 4) = o;
}

// ---------------- launcher (single stream, R7 structure) ----------------
static inline unsigned cdivu(long a, long b) { return (unsigned)((a + b - 1) / b); }

extern "C" void kernel_launch(void* const* d_in, const int* in_sizes, int n_in,
                              void* d_out, int out_size) {
    const float* xb  = (const float*)d_in[0];
    const float* xc  = (const float*)d_in[1];
    const float* xt  = (const float*)d_in[2];
    const float* Ws1 = (const float*)d_in[3];
    const float* Wd1 = (const float*)d_in[4];
    const float* as1 = (const float*)d_in[5];
    const float* ad1 = (const float*)d_in[6];
    const float* b1  = (const float*)d_in[7];
    const float* Ws2 = (const float*)d_in[8];
    const float* Wd2 = (const float*)d_in[9];
    const float* as2 = (const float*)d_in[10];
    const float* ad2 = (const float*)d_in[11];
    const float* b2  = (const float*)d_in[12];
    const float* Wg  = (const float*)d_in[13];
    const float* bg  = (const float*)d_in[14];
    const int* b2c_src = (const int*)d_in[15];
    const int* b2c_dst = (const int*)d_in[16];
    const int* c2t_src = (const int*)d_in[17];
    const int* c2t_dst = (const int*)d_in[18];
    const int* adj_src = (const int*)d_in[19];
    const int* adj_dst = (const int*)d_in[20];

    int Nb = in_sizes[0] / 128, Nc = in_sizes[1] / 128, Nt = in_sizes[2] / 128;
    int Ebc = in_sizes[15], Ect = in_sizes[17], Eadj = in_sizes[19];

    float* out   = (float*)d_out;
    float* out_b = out;
    float* out_c = out + (size_t)Nb * 128;
    float* out_t = out_c + (size_t)Nc * 128;

    void* p;
    cudaGetSymbolAddress(&p, g_hs);    __nv_bfloat16* hs = (__nv_bfloat16*)p;
    cudaGetSymbolAddress(&p, g_xw);    __nv_bfloat16* xw = (__nv_bfloat16*)p;
    cudaGetSymbolAddress(&p, g_es);    float* es   = (float*)p;
    cudaGetSymbolAddress(&p, g_ed);    float* ed   = (float*)p;
    cudaGetSymbolAddress(&p, g_edt);   float* edt  = (float*)p;
    cudaGetSymbolAddress(&p, g_sb);    float* sbuf = (float*)p;
    cudaGetSymbolAddress(&p, g_wb);    float* wbuf = (float*)p;
    cudaGetSymbolAddress(&p, g_dinv);  float* dinv = (float*)p;
    cudaGetSymbolAddress(&p, g_cntc);  int* cntc = (int*)p;
    cudaGetSymbolAddress(&p, g_offc);  int* offc = (int*)p;
    cudaGetSymbolAddress(&p, g_cntb);  int* cntb = (int*)p;
    cudaGetSymbolAddress(&p, g_offb);  int* offb = (int*)p;
    cudaGetSymbolAddress(&p, g_csrc_c); int* csrcc = (int*)p;
    cudaGetSymbolAddress(&p, g_csrc_b); int* csrcb = (int*)p;
    cudaGetSymbolAddress(&p, g_bsum);  int* bsum = (int*)p;
    cudaGetSymbolAddress(&p, g_v2a);   float* v2a = (float*)p;
    cudaGetSymbolAddress(&p, g_v2b);   float* v2b = (float*)p;
    cudaGetSymbolAddress(&p, g_wt1);   float* wt1 = (float*)p;
    cudaGetSymbolAddress(&p, g_wt2);   float* wt2 = (float*)p;
    cudaGetSymbolAddress(&p, g_wtg);   float* wtg = (float*)p;

    cudaFuncSetAttribute(gemm_mma, cudaFuncAttributeMaxDynamicSharedMemorySize, MMA_SMEM);
    cudaFuncSetAttribute(gemm_dual, cudaFuncAttributeMaxDynamicSharedMemorySize, MMA_SMEM);

    // ---- critical path, single stream ----
    transpose_w3<<<dim3(4, 4, 3), dim3(32, 8)>>>(Ws1, Ws2, Wg, wt1, wt2, wtg);
    gemm_dual<<<cdivu(Nb, 128), 256, MMA_SMEM>>>(xb, wt1, wtg, hs, xw, Nb, es, as1);

    precompute_v2<<<2, 128>>>(Wd1, ad1, Wd2, ad2, v2a, v2b);
    node_alpha<<<cdivu((long)Nc * 32, 256), 256>>>(xc, v2a, ed, Nc);
    node_alpha<<<cdivu((long)Nt * 32, 256), 256>>>(xt, v2b, edt, Nt);
    cudaMemsetAsync(sbuf, 0, (size_t)Nt * 4 * sizeof(float), 0);

    // GAT1 CSR build (over Nc)
    int NCb = cdivu(Nc, SCAN_B);
    cudaMemsetAsync(cntc, 0, (size_t)Nc * sizeof(int), 0);
    count_dst<<<cdivu(Ebc, 256), 256>>>(b2c_dst, cntc, Ebc);
    scan1<<<NCb, SCAN_B>>>(cntc, offc, bsum, Nc);
    scan2<<<1, 1024>>>(bsum, NCb);
    scan3<<<NCb, SCAN_B>>>(cntc, offc, bsum, (float*)nullptr, Nc, Ebc);
    edge_w_fill<<<cdivu(Ebc, 256), 256>>>(es, ed, b2c_src, b2c_dst, cntc, csrcc, wbuf, Ebc);
    gat_csr<<<cdivu((long)Nc * 32, 256), 256>>>(offc, csrcc, wbuf, hs, xc, b1, out_c, Nc);

    // GAT2: cable -> transformer (COO, small)
    gemm_mma<<<cdivu(Nc, 128), 256, MMA_SMEM>>>(out_c, wt2, hs, Nc, es, as2);
    edge_w<<<cdivu(Ect, 256), 256>>>(es, edt, c2t_src, c2t_dst, wbuf, sbuf, Ect);
    init_half_bias<<<cdivu((long)Nt * 32, 256), 256>>>(xt, b2, out_t, Nt);
    edge_aggr<<<cdivu((long)Ect * 32, 256), 256>>>(wbuf, sbuf, c2t_src, c2t_dst, hs, out_t, Ect);

    // GCN CSR build (over Nb) + finalize
    int NBb = cdivu(Nb, SCAN_B);
    cudaMemsetAsync(cntb, 0, (size_t)Nb * sizeof(int), 0);
    count_dst<<<cdivu(Eadj, 256), 256>>>(adj_dst, cntb, Eadj);
    scan1<<<NBb, SCAN_B>>>(cntb, offb, bsum, Nb);
    scan2<<<1, 1024>>>(bsum, NBb);
    scan3<<<NBb, SCAN_B>>>(cntb, offb, bsum, dinv, Nb, Eadj);
    fill_csr<<<cdivu(Eadj, 256), 256>>>(adj_src, adj_dst, cntb, csrcb, Eadj);
    gcn_csr<<<cdivu((long)Nb * 32, 256), 256>>>(offb, csrcb, dinv, xw, xb, bg, out_b, Nb);
}

// round 17
// speedup vs baseline: 1.1220x; 1.0046x over previous
#include <cuda_runtime.h>
#include <cuda_bf16.h>
#include <cstdint>

// ---------------- scratch (device globals; no allocations allowed) ----------------
#define MAXNB 200000
#define MAXNC 20000
#define MAXNT 2000
#define MAXE_GAT 200000
#define MAXE_ADJ 1600000
#define SCAN_B 512

__device__ __nv_bfloat16 g_hs[(size_t)MAXNB * 128];  // hs1, later hs2
__device__ __nv_bfloat16 g_xw[(size_t)MAXNB * 128];  // GCN xw
__device__ float g_es[(size_t)MAXNB * 4];
__device__ float g_ed[(size_t)MAXNC * 4];
__device__ float g_edt[(size_t)MAXNT * 4];
__device__ float g_sb[(size_t)MAXNT * 4];
__device__ float g_wb[(size_t)MAXE_GAT * 4];
__device__ float g_dinv[MAXNB];
__device__ int g_cntc[MAXNC];
__device__ int g_offc[MAXNC + 1];
__device__ int g_cntb[MAXNB];
__device__ int g_offb[MAXNB + 1];
__device__ int g_csrc_c[MAXE_GAT];
__device__ int g_csrc_b[MAXE_ADJ];
__device__ int g_bsum[1024];
__device__ float g_v2a[128 * 4];
__device__ float g_v2b[128 * 4];
__device__ float g_wt1[128 * 128];
__device__ float g_wt2[128 * 128];
__device__ float g_wtg[128 * 128];

static __device__ __forceinline__ void red_add_v4(float* addr, float x, float y, float z, float w) {
    asm volatile("red.global.add.v4.f32 [%0], {%1,%2,%3,%4};"
                 :: "l"(addr), "f"(x), "f"(y), "f"(z), "f"(w) : "memory");
}

static __device__ __forceinline__ unsigned bf2pack(float c0, float c1) {
    unsigned r;
    asm("cvt.rn.bf16x2.f32 %0, %1, %2;" : "=r"(r) : "f"(c1), "f"(c0));
    return r;
}

static __device__ __forceinline__ uint32_t tf32r(float v) {
    uint32_t r;
    asm("cvt.rna.tf32.f32 %0, %1;" : "=r"(r) : "f"(v));
    return r;
}

// 3 weights transposed ([n][k]) + tf32-rounded, selected by blockIdx.z
__global__ void transpose_w3(const float* __restrict__ W0, const float* __restrict__ W1,
                             const float* __restrict__ W2, float* __restrict__ T0,
                             float* __restrict__ T1, float* __restrict__ T2) {
    const float* W = blockIdx.z == 0 ? W0 : (blockIdx.z == 1 ? W1 : W2);
    float* T = blockIdx.z == 0 ? T0 : (blockIdx.z == 1 ? T1 : T2);
    __shared__ float t[32][33];
    int bx = blockIdx.x * 32, by = blockIdx.y * 32;
#pragma unroll
    for (int j = 0; j < 32; j += 8)
        t[threadIdx.y + j][threadIdx.x] =
            __uint_as_float(tf32r(W[(size_t)(by + threadIdx.y + j) * 128 + bx + threadIdx.x]));
    __syncthreads();
#pragma unroll
    for (int j = 0; j < 32; j += 8)
        T[(size_t)(bx + threadIdx.y + j) * 128 + by + threadIdx.x] = t[threadIdx.x][threadIdx.y + j];
}

__global__ void precompute_v2(const float* __restrict__ Wd1, const float* __restrict__ ad1,
                              const float* __restrict__ Wd2, const float* __restrict__ ad2,
                              float* __restrict__ Va, float* __restrict__ Vb) {
    const float* W = blockIdx.x == 0 ? Wd1 : Wd2;
    const float* a = blockIdx.x == 0 ? ad1 : ad2;
    float* V = blockIdx.x == 0 ? Va : Vb;
    int d = threadIdx.x;
    float s[4] = {0.f, 0.f, 0.f, 0.f};
#pragma unroll
    for (int h = 0; h < 4; h++)
        for (int c = 0; c < 32; c++)
            s[h] += W[d * 128 + h * 32 + c] * a[h * 32 + c];
    ((float4*)V)[d] = make_float4(s[0], s[1], s[2], s[3]);
}

// ---------------- tf32 mma.sync GEMMs (32-row x 64-col warp tiles; R11 config) ------
#define AP 132
#define MMA_SMEM ((128 * AP * 2) * 4)

static __device__ __forceinline__ void mma_loop32(const uint32_t* __restrict__ Asu,
                                                  const uint32_t* __restrict__ Wsu,
                                                  int ar0, int bbase, int t,
                                                  float acc[2][8][4]) {
    int ar1 = ar0 + 8 * AP, ar2 = ar0 + 16 * AP, ar3 = ar0 + 24 * AP;
#pragma unroll 2
    for (int ks = 0; ks < 16; ks++) {
        int k0 = ks * 8;
        uint32_t a00 = Asu[ar0 + k0 + t];
        uint32_t a01 = Asu[ar1 + k0 + t];
        uint32_t a02 = Asu[ar0 + k0 + t + 4];
        uint32_t a03 = Asu[ar1 + k0 + t + 4];
        uint32_t a10 = Asu[ar2 + k0 + t];
        uint32_t a11 = Asu[ar3 + k0 + t];
        uint32_t a12 = Asu[ar2 + k0 + t + 4];
        uint32_t a13 = Asu[ar3 + k0 + t + 4];
#pragma unroll
        for (int nt = 0; nt < 8; nt++) {
            uint32_t b0 = Wsu[bbase + nt * 8 * AP + k0 + t];
            uint32_t b1 = Wsu[bbase + nt * 8 * AP + k0 + t + 4];
            asm("mma.sync.aligned.m16n8k8.row.col.f32.tf32.tf32.f32 "
                "{%0,%1,%2,%3}, {%4,%5,%6,%7}, {%8,%9}, {%0,%1,%2,%3};"
                : "+f"(acc[0][nt][0]), "+f"(acc[0][nt][1]), "+f"(acc[0][nt][2]), "+f"(acc[0][nt][3])
                : "r"(a00), "r"(a01), "r"(a02), "r"(a03), "r"(b0), "r"(b1));
            asm("mma.sync.aligned.m16n8k8.row.col.f32.tf32.tf32.f32 "
                "{%0,%1,%2,%3}, {%4,%5,%6,%7}, {%8,%9}, {%0,%1,%2,%3};"
                : "+f"(acc[1][nt][0]), "+f"(acc[1][nt][1]), "+f"(acc[1][nt][2]), "+f"(acc[1][nt][3])
                : "r"(a10), "r"(a11), "r"(a12), "r"(a13), "r"(b0), "r"(b1));
        }
    }
}

static __device__ __forceinline__ void mma_epilogue32(float acc[2][8][4], __nv_bfloat16* C,
                                                      int M, int brow, int wr, int wc,
                                                      int g, int t, float* es_out,
                                                      const float* a_s) {
    int grow[4];
    grow[0] = brow + wr * 32 + g;
    grow[1] = grow[0] + 8;
    grow[2] = grow[0] + 16;
    grow[3] = grow[0] + 24;
    bool okr[4];
#pragma unroll
    for (int s = 0; s < 4; s++) okr[s] = grow[s] < M;
    bool do_es = es_out != nullptr;
    float sv[4][2] = {{0.f, 0.f}, {0.f, 0.f}, {0.f, 0.f}, {0.f, 0.f}};
#pragma unroll
    for (int mg = 0; mg < 2; mg++) {
#pragma unroll
        for (int nt = 0; nt < 8; nt++) {
            float c0 = acc[mg][nt][0], c1 = acc[mg][nt][1];
            float c2 = acc[mg][nt][2], c3 = acc[mg][nt][3];
            int col = wc * 64 + nt * 8 + 2 * t;
            if (okr[mg * 2])
                *(unsigned*)(C + (size_t)grow[mg * 2] * 128 + col) = bf2pack(c0, c1);
            if (okr[mg * 2 + 1])
                *(unsigned*)(C + (size_t)grow[mg * 2 + 1] * 128 + col) = bf2pack(c2, c3);
            if (do_es) {
                int hl = nt >> 2;
                int cb = (wc * 2 + hl) * 32 + (nt & 3) * 8 + 2 * t;
                float av0 = __ldg(a_s + cb), av1 = __ldg(a_s + cb + 1);
                sv[mg * 2][hl]     += c0 * av0 + c1 * av1;
                sv[mg * 2 + 1][hl] += c2 * av0 + c3 * av1;
            }
        }
    }
    if (do_es) {
#pragma unroll
        for (int s = 0; s < 4; s++) {
#pragma unroll
            for (int hl = 0; hl < 2; hl++) {
                sv[s][hl] += __shfl_down_sync(~0u, sv[s][hl], 1);
                sv[s][hl] += __shfl_down_sync(~0u, sv[s][hl], 2);
            }
        }
        if (t == 0) {
#pragma unroll
            for (int s = 0; s < 4; s++) {
                if (okr[s])
                    *(float2*)(es_out + (size_t)grow[s] * 4 + wc * 2) =
                        make_float2(sv[s][0], sv[s][1]);
            }
        }
    }
}

__global__ void __launch_bounds__(256, 1)
gemm_mma(const float* __restrict__ A, const float* __restrict__ Wt,
         __nv_bfloat16* __restrict__ C, int M,
         float* __restrict__ es_out, const float* __restrict__ a_s) {
    extern __shared__ float smem[];
    float* As = smem;
    float* Ws = smem + 128 * AP;
    int tid = threadIdx.x;
    int brow = blockIdx.x * 128;
    {
        int row = tid & 127;
        int k0 = (tid >> 7) * 64;
        int grow = brow + row;
        bool ok = grow < M;
        const float4* Ar = (const float4*)(A + (size_t)grow * 128 + k0);
        const float4* Wr = (const float4*)(Wt + (size_t)row * 128 + k0);
#pragma unroll
        for (int i = 0; i < 16; i++) {
            float4 v = make_float4(0.f, 0.f, 0.f, 0.f);
            if (ok) v = Ar[i];
            uint4 tv;
            tv.x = tf32r(v.x); tv.y = tf32r(v.y); tv.z = tf32r(v.z); tv.w = tf32r(v.w);
            *(uint4*)(As + row * AP + k0 + i * 4) = tv;
            *(float4*)(Ws + row * AP + k0 + i * 4) = Wr[i];
        }
    }
    __syncthreads();

    int wid = tid >> 5, lane = tid & 31;
    int g = lane >> 2, t = lane & 3;
    int wr = wid >> 1, wc = wid & 1;
    float acc[2][8][4];
#pragma unroll
    for (int mg = 0; mg < 2; mg++)
#pragma unroll
        for (int nt = 0; nt < 8; nt++)
#pragma unroll
            for (int j = 0; j < 4; j++) acc[mg][nt][j] = 0.f;
    mma_loop32((const uint32_t*)As, (const uint32_t*)Ws,
               (wr * 32 + g) * AP, (wc * 64 + g) * AP, t, acc);
    mma_epilogue32(acc, C, M, brow, wr, wc, g, t, es_out, a_s);
}

__global__ void __launch_bounds__(256, 1)
gemm_dual(const float* __restrict__ A, const float* __restrict__ Wt0,
          const float* __restrict__ Wt1, __nv_bfloat16* __restrict__ C0,
          __nv_bfloat16* __restrict__ C1, int M,
          float* __restrict__ es_out, const float* __restrict__ a_s) {
    extern __shared__ float smem[];
    float* As = smem;
    float* Ws = smem + 128 * AP;
    int tid = threadIdx.x;
    int brow = blockIdx.x * 128;
    int row = tid & 127;
    int k0 = (tid >> 7) * 64;
    {
        int grow = brow + row;
        bool ok = grow < M;
        const float4* Ar = (const float4*)(A + (size_t)grow * 128 + k0);
#pragma unroll
        for (int i = 0; i < 16; i++) {
            float4 v = make_float4(0.f, 0.f, 0.f, 0.f);
            if (ok) v = Ar[i];
            uint4 tv;
            tv.x = tf32r(v.x); tv.y = tf32r(v.y); tv.z = tf32r(v.z); tv.w = tf32r(v.w);
            *(uint4*)(As + row * AP + k0 + i * 4) = tv;
        }
    }

    int wid = tid >> 5, lane = tid & 31;
    int g = lane >> 2, t = lane & 3;
    int wr = wid >> 1, wc = wid & 1;
    int ar0 = (wr * 32 + g) * AP;
    int bbase = (wc * 64 + g) * AP;

#pragma unroll
    for (int p = 0; p < 2; p++) {
        const float* Wt = p == 0 ? Wt0 : Wt1;
        {
            const float4* Wr = (const float4*)(Wt + (size_t)row * 128 + k0);
#pragma unroll
            for (int i = 0; i < 16; i++)
                *(float4*)(Ws + row * AP + k0 + i * 4) = Wr[i];
        }
        __syncthreads();
        float acc[2][8][4];
#pragma unroll
        for (int mg = 0; mg < 2; mg++)
#pragma unroll
            for (int nt = 0; nt < 8; nt++)
#pragma unroll
                for (int j = 0; j < 4; j++) acc[mg][nt][j] = 0.f;
        mma_loop32((const uint32_t*)As, (const uint32_t*)Ws, ar0, bbase, t, acc);
        __syncthreads();  // safe to overwrite Ws next phase
        mma_epilogue32(acc, p == 0 ? C0 : C1, M, brow, wr, wc, g, t,
                       p == 0 ? es_out : (float*)nullptr, a_s);
    }
}

// out[n,h] = x[n,:] @ V[:,h]   (warp per 2 nodes; both row LDGs in flight)
__global__ void node_alpha(const float* __restrict__ X, const float* __restrict__ V,
                           float* __restrict__ out, int N) {
    int gt = blockIdx.x * blockDim.x + threadIdx.x;
    int w = gt >> 5, lane = gt & 31;
    int n0 = w * 2, n1 = n0 + 1;
    if (n0 >= N) return;
    bool has1 = n1 < N;
    float4 x0 = ((const float4*)(X + (size_t)n0 * 128))[lane];
    float4 x1 = has1 ? ((const float4*)(X + (size_t)n1 * 128))[lane]
                     : make_float4(0.f, 0.f, 0.f, 0.f);
    const float4* Vv = (const float4*)V;
    float4 v0 = Vv[lane * 4 + 0], v1 = Vv[lane * 4 + 1];
    float4 v2 = Vv[lane * 4 + 2], v3 = Vv[lane * 4 + 3];
    float p0 = x0.x * v0.x + x0.y * v1.x + x0.z * v2.x + x0.w * v3.x;
    float p1 = x0.x * v0.y + x0.y * v1.y + x0.z * v2.y + x0.w * v3.y;
    float p2 = x0.x * v0.z + x0.y * v1.z + x0.z * v2.z + x0.w * v3.z;
    float p3 = x0.x * v0.w + x0.y * v1.w + x0.z * v2.w + x0.w * v3.w;
    float q0 = x1.x * v0.x + x1.y * v1.x + x1.z * v2.x + x1.w * v3.x;
    float q1 = x1.x * v0.y + x1.y * v1.y + x1.z * v2.y + x1.w * v3.y;
    float q2 = x1.x * v0.z + x1.y * v1.z + x1.z * v2.z + x1.w * v3.z;
    float q3 = x1.x * v0.w + x1.y * v1.w + x1.z * v2.w + x1.w * v3.w;
#pragma unroll
    for (int off = 16; off; off >>= 1) {
        p0 += __shfl_down_sync(~0u, p0, off);
        p1 += __shfl_down_sync(~0u, p1, off);
        p2 += __shfl_down_sync(~0u, p2, off);
        p3 += __shfl_down_sync(~0u, p3, off);
        q0 += __shfl_down_sync(~0u, q0, off);
        q1 += __shfl_down_sync(~0u, q1, off);
        q2 += __shfl_down_sync(~0u, q2, off);
        q3 += __shfl_down_sync(~0u, q3, off);
    }
    if (lane == 0) {
        ((float4*)out)[n0] = make_float4(p0, p1, p2, p3);
        if (has1) ((float4*)out)[n1] = make_float4(q0, q1, q2, q3);
    }
}

static __device__ __forceinline__ float4 edge_w4(const float* es, const float* ed, int s, int d) {
    float4 a = ((const float4*)es)[s];
    float4 b = ((const float4*)ed)[d];
    float t0 = a.x + b.x, t1 = a.y + b.y, t2 = a.z + b.z, t3 = a.w + b.w;
    t0 = t0 > 0.f ? t0 : 0.2f * t0;
    t1 = t1 > 0.f ? t1 : 0.2f * t1;
    t2 = t2 > 0.f ? t2 : 0.2f * t2;
    t3 = t3 > 0.f ? t3 : 0.2f * t3;
    return make_float4(__expf(t0), __expf(t1), __expf(t2), __expf(t3));
}

// COO edge_w for GAT2 (small)
__global__ void edge_w(const float* __restrict__ es, const float* __restrict__ ed,
                       const int* __restrict__ src, const int* __restrict__ dst,
                       float* __restrict__ w, float* __restrict__ ssum, int E) {
    int e = blockIdx.x * blockDim.x + threadIdx.x;
    if (e >= E) return;
    int s = src[e], d = dst[e];
    float4 wv = edge_w4(es, ed, s, d);
    ((float4*)w)[e] = wv;
    red_add_v4(ssum + (size_t)d * 4, wv.x, wv.y, wv.z, wv.w);
}

// CSR edge_w + fill for GAT1
__global__ void edge_w_fill(const float* __restrict__ es, const float* __restrict__ ed,
                            const int* __restrict__ src, const int* __restrict__ dst,
                            int* __restrict__ cursor, int* __restrict__ csrc,
                            float* __restrict__ w, int E) {
    int e = blockIdx.x * blockDim.x + threadIdx.x;
    if (e >= E) return;
    int s = src[e], d = dst[e];
    float4 wv = edge_w4(es, ed, s, d);
    int p = atomicAdd(cursor + d, 1);
    csrc[p] = s;
    ((float4*)w)[p] = wv;
}

// warp per dst node: softmax-sum + gather + finalize
// 2 rows per iteration (R13 MLP); weights loaded directly per-head (no shuffles).
__global__ void gat_csr(const int* __restrict__ off, const int* __restrict__ csrc,
                        const float* __restrict__ wbuf, const __nv_bfloat16* __restrict__ hs,
                        const float* __restrict__ xdst, const float* __restrict__ bias,
                        float* __restrict__ out, int N) {
    int gt = blockIdx.x * blockDim.x + threadIdx.x;
    int n = gt >> 5, lane = gt & 31;
    if (n >= N) return;
    int o0 = off[n], o1 = off[n + 1];
    float sw0 = 0.f, sw1 = 0.f, sw2 = 0.f, sw3 = 0.f;
    for (int e = o0 + lane; e < o1; e += 32) {
        float4 w = ((const float4*)wbuf)[e];
        sw0 += w.x; sw1 += w.y; sw2 += w.z; sw3 += w.w;
    }
#pragma unroll
    for (int o = 16; o; o >>= 1) {
        sw0 += __shfl_xor_sync(~0u, sw0, o);
        sw1 += __shfl_xor_sync(~0u, sw1, o);
        sw2 += __shfl_xor_sync(~0u, sw2, o);
        sw3 += __shfl_xor_sync(~0u, sw3, o);
    }
    int h = lane >> 3;
    float stot = (h < 2) ? (h == 0 ? sw0 : sw1) : (h == 2 ? sw2 : sw3);
    float kinv = 0.5f / (stot + 1e-16f);
    float a0 = 0.f, a1 = 0.f, a2 = 0.f, a3 = 0.f;
    for (int base = o0; base < o1; base += 32) {
        int eidx = base + lane;
        bool v = eidx < o1;
        int s_l = v ? csrc[eidx] : 0;
        int cntc = min(32, o1 - base);
        int j = 0;
        for (; j + 1 < cntc; j += 2) {
            int sa = __shfl_sync(~0u, s_l, j);
            int sb = __shfl_sync(~0u, s_l, j + 1);
            float ka = wbuf[(size_t)(base + j) * 4 + h];
            float kb = wbuf[(size_t)(base + j + 1) * 4 + h];
            uint2 ra = *(const uint2*)(hs + (size_t)sa * 128 + lane * 4);
            uint2 rb = *(const uint2*)(hs + (size_t)sb * 128 + lane * 4);
            ka *= kinv; kb *= kinv;
            float2 fa0 = __bfloat1622float2(*(const __nv_bfloat162*)&ra.x);
            float2 fa1 = __bfloat1622float2(*(const __nv_bfloat162*)&ra.y);
            float2 fb0 = __bfloat1622float2(*(const __nv_bfloat162*)&rb.x);
            float2 fb1 = __bfloat1622float2(*(const __nv_bfloat162*)&rb.y);
            a0 += ka * fa0.x + kb * fb0.x;
            a1 += ka * fa0.y + kb * fb0.y;
            a2 += ka * fa1.x + kb * fb1.x;
            a3 += ka * fa1.y + kb * fb1.y;
        }
        if (j < cntc) {
            int s = __shfl_sync(~0u, s_l, j);
            float k = wbuf[(size_t)(base + j) * 4 + h] * kinv;
            uint2 raw = *(const uint2*)(hs + (size_t)s * 128 + lane * 4);
            float2 f0 = __bfloat1622float2(*(const __nv_bfloat162*)&raw.x);
            float2 f1 = __bfloat1622float2(*(const __nv_bfloat162*)&raw.y);
            a0 += k * f0.x; a1 += k * f0.y; a2 += k * f1.x; a3 += k * f1.y;
        }
    }
    float4 xv = *(const float4*)(xdst + (size_t)n * 128 + lane * 4);
    float4 bv = *(const float4*)(bias + lane * 4);
    float4 o;
    o.x = xv.x + 0.5f * bv.x + a0;
    o.y = xv.y + 0.5f * bv.y + a1;
    o.z = xv.z + 0.5f * bv.z + a2;
    o.w = xv.w + 0.5f * bv.w + a3;
    *(float4*)(out + (size_t)n * 128 + lane * 4) = o;
}

// warp per edge: out[dst] += 0.5 * alpha * hs_bf16[src]  (COO, GAT2)
__global__ void edge_aggr(const float* __restrict__ w, const float* __restrict__ ssum,
                          const int* __restrict__ src, const int* __restrict__ dst,
                          const __nv_bfloat16* __restrict__ hs, float* __restrict__ out, int E) {
    int gt = blockIdx.x * blockDim.x + threadIdx.x;
    int e = gt >> 5, lane = gt & 31;
    if (e >= E) return;
    int s = src[e], d = dst[e];
    int h = lane >> 3;
    float alpha = w[(size_t)e * 4 + h] / (ssum[(size_t)d * 4 + h] + 1e-16f);
    float k = 0.5f * alpha;
    uint2 raw = *(const uint2*)(hs + (size_t)s * 128 + lane * 4);
    float2 f0 = __bfloat1622float2(*(const __nv_bfloat162*)&raw.x);
    float2 f1 = __bfloat1622float2(*(const __nv_bfloat162*)&raw.y);
    red_add_v4(out + (size_t)d * 128 + lane * 4, k * f0.x, k * f0.y, k * f1.x, k * f1.y);
}

// out[n,c] = x[n,c] + 0.5*b[c]
__global__ void init_half_bias(const float* __restrict__ x, const float* __restrict__ b,
                               float* __restrict__ out, int N) {
    int i = blockIdx.x * blockDim.x + threadIdx.x;
    if (i >= N * 32) return;
    float4 xv = ((const float4*)x)[i];
    float4 bv = ((const float4*)b)[i & 31];
    ((float4*)out)[i] = make_float4(xv.x + 0.5f * bv.x, xv.y + 0.5f * bv.y,
                                    xv.z + 0.5f * bv.z, xv.w + 0.5f * bv.w);
}

// ---------------- CSR build ----------------
__global__ void count_dst(const int* __restrict__ dst, int* __restrict__ cnt, int E) {
    int e = blockIdx.x * blockDim.x + threadIdx.x;
    if (e < E) atomicAdd(cnt + dst[e], 1);
}

__global__ void scan1(const int* __restrict__ cnt, int* __restrict__ incl,
                      int* __restrict__ bsum, int N) {
    int i = blockIdx.x * SCAN_B + threadIdx.x;
    int lane = threadIdx.x & 31, wid = threadIdx.x >> 5;
    int v = (i < N) ? cnt[i] : 0;
    int x = v;
#pragma unroll
    for (int o = 1; o < 32; o <<= 1) {
        int t = __shfl_up_sync(~0u, x, o);
        if (lane >= o) x += t;
    }
    __shared__ int wtot[16];
    if (lane == 31) wtot[wid] = x;
    __syncthreads();
    if (wid == 0) {
        int t = (lane < 16) ? wtot[lane] : 0;
#pragma unroll
        for (int o = 1; o < 16; o <<= 1) {
            int u = __shfl_up_sync(~0u, t, o);
            if (lane >= o) t += u;
        }
        if (lane < 16) wtot[lane] = t;
    }
    __syncthreads();
    int base = (wid > 0) ? wtot[wid - 1] : 0;
    int inclv = x + base;
    if (i < N) incl[i] = inclv;
    if (threadIdx.x == SCAN_B - 1) bsum[blockIdx.x] = inclv;
}

__global__ void scan2(int* __restrict__ bsum, int NB) {
    int i = threadIdx.x;
    int lane = i & 31, wid = i >> 5;
    int v = (i < NB) ? bsum[i] : 0;
    int x = v;
#pragma unroll
    for (int o = 1; o < 32; o <<= 1) {
        int t = __shfl_up_sync(~0u, x, o);
        if (lane >= o) x += t;
    }
    __shared__ int wtot[32];
    if (lane == 31) wtot[wid] = x;
    __syncthreads();
    if (wid == 0) {
        int t = wtot[lane];
#pragma unroll
        for (int o = 1; o < 32; o <<= 1) {
            int u = __shfl_up_sync(~0u, t, o);
            if (lane >= o) t += u;
        }
        wtot[lane] = t;
    }
    __syncthreads();
    int base = (wid > 0) ? wtot[wid - 1] : 0;
    if (i < NB) bsum[i] = x + base - v;
}

__global__ void scan3(int* __restrict__ cnt_cursor, int* __restrict__ off,
                      const int* __restrict__ bsum, float* __restrict__ dinv,
                      int N, int E) {
    int i = blockIdx.x * SCAN_B + threadIdx.x;
    if (i >= N) return;
    int c = cnt_cursor[i];
    int excl = off[i] - c + bsum[blockIdx.x];
    off[i] = excl;
    cnt_cursor[i] = excl;
    if (dinv) dinv[i] = rsqrtf((float)c + 1.0f);
    if (i == N - 1) off[N] = E;
}

__global__ void fill_csr(const int* __restrict__ src, const int* __restrict__ dst,
                         int* __restrict__ cursor, int* __restrict__ csrc, int E) {
    int e = blockIdx.x * blockDim.x + threadIdx.x;
    if (e >= E) return;
    int d = dst[e];
    int p = atomicAdd(cursor + d, 1);
    csrc[p] = src[e];
}

// warp per dst node: GCN gather + finalize (2 rows per iteration; R13 validated)
__global__ void gcn_csr(const int* __restrict__ off, const int* __restrict__ csrc,
                        const float* __restrict__ dinv, const __nv_bfloat16* __restrict__ xw,
                        const float* __restrict__ xb, const float* __restrict__ bg,
                        float* __restrict__ out, int N) {
    int gt = blockIdx.x * blockDim.x + threadIdx.x;
    int n = gt >> 5, lane = gt & 31;
    if (n >= N) return;
    int o0 = off[n], o1 = off[n + 1];
    float a0 = 0.f, a1 = 0.f, a2 = 0.f, a3 = 0.f;
    for (int base = o0; base < o1; base += 32) {
        int eidx = base + lane;
        bool v = eidx < o1;
        int s_l = v ? csrc[eidx] : 0;
        float ds_l = v ? dinv[s_l] : 0.f;
        int cntc = min(32, o1 - base);
        int j = 0;
        for (; j + 1 < cntc; j += 2) {
            int sa = __shfl_sync(~0u, s_l, j);
            int sb = __shfl_sync(~0u, s_l, j + 1);
            float da = __shfl_sync(~0u, ds_l, j);
            float db = __shfl_sync(~0u, ds_l, j + 1);
            uint2 ra = *(const uint2*)(xw + (size_t)sa * 128 + lane * 4);
            uint2 rb = *(const uint2*)(xw + (size_t)sb * 128 + lane * 4);
            float2 fa0 = __bfloat1622float2(*(const __nv_bfloat162*)&ra.x);
            float2 fa1 = __bfloat1622float2(*(const __nv_bfloat162*)&ra.y);
            float2 fb0 = __bfloat1622float2(*(const __nv_bfloat162*)&rb.x);
            float2 fb1 = __bfloat1622float2(*(const __nv_bfloat162*)&rb.y);
            a0 += da * fa0.x + db * fb0.x;
            a1 += da * fa0.y + db * fb0.y;
            a2 += da * fa1.x + db * fb1.x;
            a3 += da * fa1.y + db * fb1.y;
        }
        if (j < cntc) {
            int s = __shfl_sync(~0u, s_l, j);
            float ds = __shfl_sync(~0u, ds_l, j);
            uint2 raw = *(const uint2*)(xw + (size_t)s * 128 + lane * 4);
            float2 f0 = __bfloat1622float2(*(const __nv_bfloat162*)&raw.x);
            float2 f1 = __bfloat1622float2(*(const __nv_bfloat162*)&raw.y);
            a0 += ds * f0.x; a1 += ds * f0.y; a2 += ds * f1.x; a3 += ds * f1.y;
        }
    }
    float dn = dinv[n];
    float dd = dn * dn;
    float4 xv = *(const float4*)(xb + (size_t)n * 128 + lane * 4);
    uint2 rw = *(const uint2*)(xw + (size_t)n * 128 + lane * 4);
    float2 s0 = __bfloat1622float2(*(const __nv_bfloat162*)&rw.x);
    float2 s1 = __bfloat1622float2(*(const __nv_bfloat162*)&rw.y);
    float4 bv = *(const float4*)(bg + lane * 4);
    float4 o;
    o.x = xv.x + 0.2f * (dn * a0 + dd * s0.x + bv.x);
    o.y = xv.y + 0.2f * (dn * a1 + dd * s0.y + bv.y);
    o.z = xv.z + 0.2f * (dn * a2 + dd * s1.x + bv.z);
    o.w = xv.w + 0.2f * (dn * a3 + dd * s1.y + bv.w);
    *(float4*)(out + (size_t)n * 128 + lane * 4) = o;
}

// ---------------- launcher (single stream, R7 structure) ----------------
static inline unsigned cdivu(long a, long b) { return (unsigned)((a + b - 1) / b); }

extern "C" void kernel_launch(void* const* d_in, const int* in_sizes, int n_in,
                              void* d_out, int out_size) {
    const float* xb  = (const float*)d_in[0];
    const float* xc  = (const float*)d_in[1];
    const float* xt  = (const float*)d_in[2];
    const float* Ws1 = (const float*)d_in[3];
    const float* Wd1 = (const float*)d_in[4];
    const float* as1 = (const float*)d_in[5];
    const float* ad1 = (const float*)d_in[6];
    const float* b1  = (const float*)d_in[7];
    const float* Ws2 = (const float*)d_in[8];
    const float* Wd2 = (const float*)d_in[9];
    const float* as2 = (const float*)d_in[10];
    const float* ad2 = (const float*)d_in[11];
    const float* b2  = (const float*)d_in[12];
    const float* Wg  = (const float*)d_in[13];
    const float* bg  = (const float*)d_in[14];
    const int* b2c_src = (const int*)d_in[15];
    const int* b2c_dst = (const int*)d_in[16];
    const int* c2t_src = (const int*)d_in[17];
    const int* c2t_dst = (const int*)d_in[18];
    const int* adj_src = (const int*)d_in[19];
    const int* adj_dst = (const int*)d_in[20];

    int Nb = in_sizes[0] / 128, Nc = in_sizes[1] / 128, Nt = in_sizes[2] / 128;
    int Ebc = in_sizes[15], Ect = in_sizes[17], Eadj = in_sizes[19];

    float* out   = (float*)d_out;
    float* out_b = out;
    float* out_c = out + (size_t)Nb * 128;
    float* out_t = out_c + (size_t)Nc * 128;

    void* p;
    cudaGetSymbolAddress(&p, g_hs);    __nv_bfloat16* hs = (__nv_bfloat16*)p;
    cudaGetSymbolAddress(&p, g_xw);    __nv_bfloat16* xw = (__nv_bfloat16*)p;
    cudaGetSymbolAddress(&p, g_es);    float* es   = (float*)p;
    cudaGetSymbolAddress(&p, g_ed);    float* ed   = (float*)p;
    cudaGetSymbolAddress(&p, g_edt);   float* edt  = (float*)p;
    cudaGetSymbolAddress(&p, g_sb);    float* sbuf = (float*)p;
    cudaGetSymbolAddress(&p, g_wb);    float* wbuf = (float*)p;
    cudaGetSymbolAddress(&p, g_dinv);  float* dinv = (float*)p;
    cudaGetSymbolAddress(&p, g_cntc);  int* cntc = (int*)p;
    cudaGetSymbolAddress(&p, g_offc);  int* offc = (int*)p;
    cudaGetSymbolAddress(&p, g_cntb);  int* cntb = (int*)p;
    cudaGetSymbolAddress(&p, g_offb);  int* offb = (int*)p;
    cudaGetSymbolAddress(&p, g_csrc_c); int* csrcc = (int*)p;
    cudaGetSymbolAddress(&p, g_csrc_b); int* csrcb = (int*)p;
    cudaGetSymbolAddress(&p, g_bsum);  int* bsum = (int*)p;
    cudaGetSymbolAddress(&p, g_v2a);   float* v2a = (float*)p;
    cudaGetSymbolAddress(&p, g_v2b);   float* v2b = (float*)p;
    cudaGetSymbolAddress(&p, g_wt1);   float* wt1 = (float*)p;
    cudaGetSymbolAddress(&p, g_wt2);   float* wt2 = (float*)p;
    cudaGetSymbolAddress(&p, g_wtg);   float* wtg = (float*)p;

    cudaFuncSetAttribute(gemm_mma, cudaFuncAttributeMaxDynamicSharedMemorySize, MMA_SMEM);
    cudaFuncSetAttribute(gemm_dual, cudaFuncAttributeMaxDynamicSharedMemorySize, MMA_SMEM);

    // ---- critical path, single stream ----
    transpose_w3<<<dim3(4, 4, 3), dim3(32, 8)>>>(Ws1, Ws2, Wg, wt1, wt2, wtg);
    gemm_dual<<<cdivu(Nb, 128), 256, MMA_SMEM>>>(xb, wt1, wtg, hs, xw, Nb, es, as1);

    precompute_v2<<<2, 128>>>(Wd1, ad1, Wd2, ad2, v2a, v2b);
    node_alpha<<<cdivu((long)cdivu(Nc, 2) * 32, 256), 256>>>(xc, v2a, ed, Nc);
    node_alpha<<<cdivu((long)cdivu(Nt, 2) * 32, 256), 256>>>(xt, v2b, edt, Nt);
    cudaMemsetAsync(sbuf, 0, (size_t)Nt * 4 * sizeof(float), 0);

    // GAT1 CSR build (over Nc)
    int NCb = cdivu(Nc, SCAN_B);
    cudaMemsetAsync(cntc, 0, (size_t)Nc * sizeof(int), 0);
    count_dst<<<cdivu(Ebc, 256), 256>>>(b2c_dst, cntc, Ebc);
    scan1<<<NCb, SCAN_B>>>(cntc, offc, bsum, Nc);
    scan2<<<1, 1024>>>(bsum, NCb);
    scan3<<<NCb, SCAN_B>>>(cntc, offc, bsum, (float*)nullptr, Nc, Ebc);
    edge_w_fill<<<cdivu(Ebc, 256), 256>>>(es, ed, b2c_src, b2c_dst, cntc, csrcc, wbuf, Ebc);
    gat_csr<<<cdivu((long)Nc * 32, 256), 256>>>(offc, csrcc, wbuf, hs, xc, b1, out_c, Nc);

    // GAT2: cable -> transformer (COO, small)
    gemm_mma<<<cdivu(Nc, 128), 256, MMA_SMEM>>>(out_c, wt2, hs, Nc, es, as2);
    edge_w<<<cdivu(Ect, 256), 256>>>(es, edt, c2t_src, c2t_dst, wbuf, sbuf, Ect);
    init_half_bias<<<cdivu((long)Nt * 32, 256), 256>>>(xt, b2, out_t, Nt);
    edge_aggr<<<cdivu((long)Ect * 32, 256), 256>>>(wbuf, sbuf, c2t_src, c2t_dst, hs, out_t, Ect);

    // GCN CSR build (over Nb) + finalize
    int NBb = cdivu(Nb, SCAN_B);
    cudaMemsetAsync(cntb, 0, (size_t)Nb * sizeof(int), 0);
    count_dst<<<cdivu(Eadj, 256), 256>>>(adj_dst, cntb, Eadj);
    scan1<<<NBb, SCAN_B>>>(cntb, offb, bsum, Nb);
    scan2<<<1, 1024>>>(bsum, NBb);
    scan3<<<NBb, SCAN_B>>>(cntb, offb, bsum, dinv, Nb, Eadj);
    fill_csr<<<cdivu(Eadj, 256), 256>>>(adj_src, adj_dst, cntb, csrcb, Eadj);
    gcn_csr<<<cdivu((long)Nb * 32, 256), 256>>>(offb, csrcb, dinv, xw, xb, bg, out_b, Nb);
}